// round 12
// baseline (speedup 1.0000x reference)
#include <cuda_runtime.h>
#include <cuda_fp16.h>
#include <math.h>
#include <stdint.h>

#define Bn 8
#define Cn 512
#define Tn 2048
#define CT ((size_t)Cn * Tn)
#define TT ((size_t)Tn * Tn)
#define QKC 1024                         // stacked q|k channel dim
#define QKT ((size_t)Tn * QKC)           // per-batch qk plane

typedef __half fp16;

// ---------------- scratch (static device globals; allocation-guard safe) ----
__device__ __align__(16) fp16 g_hT[Bn * Tn * Cn];    // [B,T,C] groupnormed, fp16
__device__ __align__(16) fp16 g_wqk[QKC * Cn];       // [Wq;Wk] fp16
__device__ __align__(16) fp16 g_wv[Cn * Cn];
__device__ __align__(16) fp16 g_wo[Cn * Cn];
__device__ __align__(16) float g_qkb[QKC];           // [q_b;k_b]
__device__ __align__(16) fp16 g_qk[Bn * Tn * QKC];   // [B,T,1024] q|k
__device__ __align__(16) fp16 g_vv[Bn * Cn * Tn];    // [B,C,T]
__device__ __align__(16) fp16 g_aT[Bn * Tn * Cn];    // [B,T,C]
__device__ __align__(16) fp16 g_wt[Bn * Tn * Tn];    // E = exp(scores), unnormalized
__device__ __align__(16) float g_zp[(size_t)Bn * Tn * 16];  // row-sum partials
__device__ __align__(16) float g_mean[Bn * 32];
__device__ __align__(16) float g_inv[Bn * 32];

// ---------------- PTX helpers ----------------------------------------------
__device__ __forceinline__ uint32_t s2u(const void* p) {
    uint32_t a;
    asm("{ .reg .u64 t; cvta.to.shared.u64 t, %1; cvt.u32.u64 %0, t; }"
        : "=r"(a) : "l"(p));
    return a;
}

__device__ __forceinline__ void cp16(uint32_t d, const void* s) {
    asm volatile("cp.async.cg.shared.global [%0], [%1], 16;" :: "r"(d), "l"(s) : "memory");
}

#define LDSM4(r, addr)                                                          \
    asm volatile("ldmatrix.sync.aligned.m8n8.x4.shared.b16 {%0,%1,%2,%3}, [%4];"\
        : "=r"((r)[0]), "=r"((r)[1]), "=r"((r)[2]), "=r"((r)[3]) : "r"(addr))

#define MMA16816(d, a, b0, b1)                                                  \
    asm volatile(                                                               \
        "mma.sync.aligned.m16n8k16.row.col.f32.f16.f16.f32 "                    \
        "{%0,%1,%2,%3}, {%4,%5,%6,%7}, {%8,%9}, {%0,%1,%2,%3};"                 \
        : "+f"((d)[0]), "+f"((d)[1]), "+f"((d)[2]), "+f"((d)[3])                \
        : "r"((a)[0]), "r"((a)[1]), "r"((a)[2]), "r"((a)[3]),                   \
          "r"(b0), "r"(b1))

// ---------------- GroupNorm stats -------------------------------------------
__global__ void gn_stats(const float* __restrict__ x) {
    const int bg = blockIdx.x, tid = threadIdx.x;
    const int b = bg >> 5, g = bg & 31;
    const size_t base = ((size_t)b * Cn + g * 16) * Tn;
    const float4* xv = (const float4*)(x + base);
    float s = 0.f, ss = 0.f;
    for (int i = tid; i < 8192; i += 256) {
        float4 v = xv[i];
        s += v.x + v.y + v.z + v.w;
        ss += v.x * v.x + v.y * v.y + v.z * v.z + v.w * v.w;
    }
    __shared__ float rs[256], rq[256];
    rs[tid] = s; rq[tid] = ss;
    __syncthreads();
    for (int o = 128; o > 0; o >>= 1) {
        if (tid < o) { rs[tid] += rs[tid + o]; rq[tid] += rq[tid + o]; }
        __syncthreads();
    }
    if (tid == 0) {
        float mean = rs[0] / 32768.f;
        float var = rq[0] / 32768.f - mean * mean;
        g_mean[bg] = mean;
        g_inv[bg] = rsqrtf(var + 1e-6f);
    }
}

// ---------------- GN apply + transpose -> fp16:  x[C,T] -> hT[T,C] ----------
__global__ void happly(const float* __restrict__ x, const float* __restrict__ gamma,
                       const float* __restrict__ beta) {
    __shared__ float tl[32][33];
    const int b = blockIdx.z, t0 = blockIdx.x * 32, c0 = blockIdx.y * 32;
    const int tx = threadIdx.x, ty = threadIdx.y;
#pragma unroll
    for (int k = 0; k < 4; k++) {
        int c = c0 + ty + k * 8;
        float ga = gamma[c] * g_inv[b * 32 + (c >> 4)];
        float be = beta[c] - g_mean[b * 32 + (c >> 4)] * ga;
        float v = x[((size_t)b * Cn + c) * Tn + t0 + tx];
        tl[ty + k * 8][tx] = v * ga + be;
    }
    __syncthreads();
#pragma unroll
    for (int k = 0; k < 4; k++) {
        int t = t0 + ty + k * 8;
        size_t o = ((size_t)b * Tn + t) * Cn + c0 + tx;
        g_hT[o] = __float2half_rn(tl[tx][ty + k * 8]);
    }
}

// ------- weights -> fp16 + qk bias concat, one launch -----------------------
__global__ void wconv(const float* __restrict__ qw, const float* __restrict__ kw,
                      const float* __restrict__ vw, const float* __restrict__ ow,
                      const float* __restrict__ qb, const float* __restrict__ kb) {
    const int n = Cn * Cn;
    int i = blockIdx.x * blockDim.x + threadIdx.x;
    if (i < QKC) g_qkb[i] = (i < Cn) ? qb[i] : kb[i - Cn];
    if (i >= 4 * n) return;
    int seg = i / n, j = i - seg * n;
    if (seg == 0)      g_wqk[j]     = __float2half_rn(qw[j]);
    else if (seg == 1) g_wqk[n + j] = __float2half_rn(kw[j]);
    else if (seg == 2) g_wv[j]      = __float2half_rn(vw[j]);
    else               g_wo[j]      = __float2half_rn(ow[j]);
}

// ---------------- mma.sync plain-fp16 GEMM, 3-stage pipeline ----------------
// D[m,n] = scale * A[m,k] * B[n,k]  (+bias +res)
// CTA tile 128x128, BK=64, 4 warps (2m x 2n), warp tile 64x64.
// Both operands K-major; SMEM rows 128B with XOR-16B swizzle.
// OUT_MODE: 0 = fp32 (+opt residual), 1 = fp16,
//           2 = fp16 exp(v) + per-(row,CTA) partial sums into zp,
//           3 = row-scaled by 1/Z (Z from zp) -> fp16.
#define STG_A 16384
#define STG_AB 32768
#define NSTAGE 3
#define SMEM_SZ (NSTAGE * STG_AB)   // 98304
#define NTHR 128

template <int BIAS_MODE, bool HAS_RES, int OUT_MODE>
__global__ __launch_bounds__(NTHR, 2) void tgemm(
    const fp16* __restrict__ Ah, const fp16* __restrict__ Bh,
    float* __restrict__ Cf, fp16* __restrict__ Oh,
    int K, int lda, int ldb, int ldc,
    size_t sA, size_t sB, size_t sC,
    const float* __restrict__ bias, const float* __restrict__ res, size_t sRes,
    float* __restrict__ zp, float scale) {
    extern __shared__ char smem[];
    const uint32_t sb = s2u(smem);
    const int tid = threadIdx.x, wid = tid >> 5, lane = tid & 31;
    const int m0 = blockIdx.y * 128, n0 = blockIdx.x * 128, b = blockIdx.z;
    const int wm = (wid >> 1) * 64, wn = (wid & 1) * 64;

    const char* Ap0 = (const char*)(Ah + (size_t)b * sA + (size_t)m0 * lda);
    const char* Bp0 = (const char*)(Bh + (size_t)b * sB + (size_t)n0 * ldb);

    const int S = K >> 6;
    const size_t la2 = (size_t)lda * 2, lb2 = (size_t)ldb * 2;

    auto load = [&](int s, int buf) {
        size_t kb = (size_t)s << 7;  // k0*2 bytes
        const char* Ap = Ap0 + kb;
        const char* Bp = Bp0 + kb;
        uint32_t ab = sb + buf * STG_AB;
        uint32_t bb = ab + STG_A;
#pragma unroll
        for (int j = 0; j < 8; j++) {
            int g = tid + j * NTHR;
            int r = g >> 3, c = g & 7;
            uint32_t sw = (uint32_t)(r * 128 + ((c ^ (r & 7)) << 4));
            cp16(ab + sw, Ap + (size_t)r * la2 + c * 16);
            cp16(bb + sw, Bp + (size_t)r * lb2 + c * 16);
        }
    };

    float acc[4][8][4];
#pragma unroll
    for (int i = 0; i < 4; i++)
#pragma unroll
        for (int j = 0; j < 8; j++)
#pragma unroll
            for (int q = 0; q < 4; q++) acc[i][j][q] = 0.f;

    // prologue: two stages in flight
    load(0, 0);
    asm volatile("cp.async.commit_group;");
    load(1, 1);
    asm volatile("cp.async.commit_group;");

    int cur = 0;
    for (int s = 0; s < S; s++) {
        asm volatile("cp.async.wait_group 1;");  // all but newest group landed
        __syncthreads();
        if (s + 2 < S) load(s + 2, (cur + 2) % NSTAGE);
        asm volatile("cp.async.commit_group;");  // empty commits keep window exact
        const uint32_t ab = sb + cur * STG_AB;
        const uint32_t bb = ab + STG_A;
#pragma unroll
        for (int kk = 0; kk < 4; kk++) {
            uint32_t af[4][4], bfr[4][4];
#pragma unroll
            for (int mi = 0; mi < 4; mi++) {
                int r = wm + mi * 16 + (lane & 15);
                int c = kk * 2 + (lane >> 4);
                LDSM4(af[mi], ab + r * 128 + ((c ^ (r & 7)) << 4));
            }
#pragma unroll
            for (int nj = 0; nj < 4; nj++) {
                int r = wn + nj * 16 + (lane & 7) + ((lane >> 4) << 3);
                int c = kk * 2 + ((lane >> 3) & 1);
                LDSM4(bfr[nj], bb + r * 128 + ((c ^ (r & 7)) << 4));
            }
#pragma unroll
            for (int mi = 0; mi < 4; mi++)
#pragma unroll
                for (int nj = 0; nj < 4; nj++) {
                    MMA16816(acc[mi][nj * 2 + 0], af[mi], bfr[nj][0], bfr[nj][1]);
                    MMA16816(acc[mi][nj * 2 + 1], af[mi], bfr[nj][2], bfr[nj][3]);
                }
        }
        cur = (cur + 1 == NSTAGE) ? 0 : cur + 1;
    }

    // ---------------- epilogue (register accumulators -> global) -----------
    const int qr = lane >> 2, qc = (lane & 3) * 2;

    // OUT_MODE 3: per-row 1/Z from 16 partials
    float rz[4][2];
    if (OUT_MODE == 3) {
#pragma unroll
        for (int mi = 0; mi < 4; mi++)
#pragma unroll
            for (int h = 0; h < 2; h++) {
                int m = m0 + wm + mi * 16 + h * 8 + qr;
                const float4* z4 = (const float4*)(zp + ((size_t)b * Tn + m) * 16);
                float4 a = z4[0], b4 = z4[1], c4 = z4[2], d4 = z4[3];
                float z = (a.x + a.y + a.z + a.w) + (b4.x + b4.y + b4.z + b4.w) +
                          (c4.x + c4.y + c4.z + c4.w) + (d4.x + d4.y + d4.z + d4.w);
                rz[mi][h] = 1.f / z;
            }
    }

    float rsum[4][2];
    if (OUT_MODE == 2) {
#pragma unroll
        for (int mi = 0; mi < 4; mi++)
#pragma unroll
            for (int h = 0; h < 2; h++) rsum[mi][h] = 0.f;
    }

#pragma unroll
    for (int mi = 0; mi < 4; mi++) {
#pragma unroll
        for (int ni = 0; ni < 8; ni++) {
            const int mA = m0 + wm + mi * 16 + qr;
            const int nA = n0 + wn + ni * 8 + qc;
#pragma unroll
            for (int h = 0; h < 2; h++) {
                const int m = mA + h * 8;
                float v0 = acc[mi][ni][h * 2 + 0] * scale;
                float v1 = acc[mi][ni][h * 2 + 1] * scale;
                if (BIAS_MODE == 1) { float bv = bias[m]; v0 += bv; v1 += bv; }
                if (BIAS_MODE == 2) { v0 += bias[nA]; v1 += bias[nA + 1]; }
                const size_t go = (size_t)m * ldc + nA;
                if (OUT_MODE == 2) {
                    v0 = __expf(v0);
                    v1 = __expf(v1);
                    rsum[mi][h] += v0 + v1;
                    __align__(4) fp16 ph[2] = {__float2half_rn(v0), __float2half_rn(v1)};
                    *(uint32_t*)(Oh + (size_t)b * sC + go) = *(uint32_t*)ph;
                } else if (OUT_MODE == 3) {
                    v0 *= rz[mi][h];
                    v1 *= rz[mi][h];
                    __align__(4) fp16 ph[2] = {__float2half_rn(v0), __float2half_rn(v1)};
                    *(uint32_t*)(Oh + (size_t)b * sC + go) = *(uint32_t*)ph;
                } else if (OUT_MODE == 1) {
                    __align__(4) fp16 ph[2] = {__float2half_rn(v0), __float2half_rn(v1)};
                    *(uint32_t*)(Oh + (size_t)b * sC + go) = *(uint32_t*)ph;
                } else {
                    if (HAS_RES) {
                        float2 r2 = *(const float2*)(res + (size_t)b * sRes + go);
                        v0 += r2.x; v1 += r2.y;
                    }
                    float2 o2 = {v0, v1};
                    *(float2*)(Cf + (size_t)b * sC + go) = o2;
                }
            }
        }
    }

    if (OUT_MODE == 2) {
        // reduce row partial across the 4 lanes sharing a row (lane&3)
#pragma unroll
        for (int mi = 0; mi < 4; mi++)
#pragma unroll
            for (int h = 0; h < 2; h++) {
                float v = rsum[mi][h];
                v += __shfl_xor_sync(0xffffffffu, v, 1);
                v += __shfl_xor_sync(0xffffffffu, v, 2);
                rsum[mi][h] = v;
            }
        __syncthreads();  // mainloop smem no longer needed
        float* zsm = (float*)smem;  // [128][2] : 2 n-warps per row group
        if ((lane & 3) == 0) {
#pragma unroll
            for (int mi = 0; mi < 4; mi++)
#pragma unroll
                for (int h = 0; h < 2; h++) {
                    int r = wm + mi * 16 + h * 8 + qr;
                    zsm[r * 2 + (wid & 1)] = rsum[mi][h];
                }
        }
        __syncthreads();
        float z = zsm[tid * 2] + zsm[tid * 2 + 1];
        zp[((size_t)b * Tn + m0 + tid) * 16 + blockIdx.x] = z;
    }
}

// ---------------- launch ----------------------------------------------------
// Resolve the BASE symbol only; interior offsets computed host-side.
template <typename T>
static T* sym_base(const void* sym) {
    void* p = nullptr;
    cudaGetSymbolAddress(&p, sym);
    return (T*)p;
}

// Side stream + fork/join events for V-projection overlap. Created once on the
// first (eager, uncaptured) call; no device memory involved. Fork/join via
// events is graph-capture-legal and yields parallel graph branches.
struct SideStream {
    cudaStream_t s;
    cudaEvent_t fork, join;
    SideStream() {
        cudaStreamCreateWithFlags(&s, cudaStreamNonBlocking);
        cudaEventCreateWithFlags(&fork, cudaEventDisableTiming);
        cudaEventCreateWithFlags(&join, cudaEventDisableTiming);
    }
};
static SideStream& side() {
    static SideStream ss;
    return ss;
}

extern "C" void kernel_launch(void* const* d_in, const int* in_sizes, int n_in,
                              void* d_out, int out_size) {
    const float* x = (const float*)d_in[0];
    const float* gamma = (const float*)d_in[1];
    const float* beta = (const float*)d_in[2];
    const float* q_w = (const float*)d_in[3];
    const float* q_b = (const float*)d_in[4];
    const float* k_w = (const float*)d_in[5];
    const float* k_b = (const float*)d_in[6];
    const float* v_w = (const float*)d_in[7];
    const float* v_b = (const float*)d_in[8];
    const float* o_w = (const float*)d_in[9];
    const float* o_b = (const float*)d_in[10];
    float* out = (float*)d_out;

    cudaFuncSetAttribute(tgemm<2, false, 1>, cudaFuncAttributeMaxDynamicSharedMemorySize, SMEM_SZ);
    cudaFuncSetAttribute(tgemm<1, false, 1>, cudaFuncAttributeMaxDynamicSharedMemorySize, SMEM_SZ);
    cudaFuncSetAttribute(tgemm<0, false, 2>, cudaFuncAttributeMaxDynamicSharedMemorySize, SMEM_SZ);
    cudaFuncSetAttribute(tgemm<0, false, 3>, cudaFuncAttributeMaxDynamicSharedMemorySize, SMEM_SZ);
    cudaFuncSetAttribute(tgemm<1, true, 0>, cudaFuncAttributeMaxDynamicSharedMemorySize, SMEM_SZ);

    fp16* hT = sym_base<fp16>(g_hT);
    fp16* wqk = sym_base<fp16>(g_wqk);
    fp16* wv = sym_base<fp16>(g_wv);
    fp16* wo = sym_base<fp16>(g_wo);
    fp16* qk = sym_base<fp16>(g_qk);
    fp16* vv = sym_base<fp16>(g_vv);
    fp16* aT = sym_base<fp16>(g_aT);
    fp16* wt = sym_base<fp16>(g_wt);
    float* zp = sym_base<float>(g_zp);
    float* qkb = sym_base<float>(g_qkb);

    SideStream& ss = side();

    // serial preamble on the capture (default) stream
    wconv<<<(4 * Cn * Cn + 255) / 256, 256>>>(q_w, k_w, v_w, o_w, q_b, k_b);
    gn_stats<<<Bn * 32, 256>>>(x);
    happly<<<dim3(Tn / 32, Cn / 32, Bn), dim3(32, 8)>>>(x, gamma, beta);

    // fork: V-projection runs on the side stream, overlapping QK + scores
    cudaEventRecord(ss.fork, 0);
    cudaStreamWaitEvent(ss.s, ss.fork, 0);
    dim3 gV(Tn / 128, Cn / 128, Bn);
    tgemm<1, false, 1><<<gV, NTHR, SMEM_SZ, ss.s>>>(
        wv, hT, nullptr, vv,
        Cn, Cn, Cn, Tn, 0, CT, CT, v_b, nullptr, 0, nullptr, 1.f);
    cudaEventRecord(ss.join, ss.s);

    // main chain: merged Q|K projection -> qk[B,T,1024] fp16
    dim3 gQK(QKC / 128, Tn / 128, Bn);
    tgemm<2, false, 1><<<gQK, NTHR, SMEM_SZ>>>(
        hT, wqk, nullptr, qk,
        Cn, Cn, Cn, QKC, CT, 0, QKT, qkb, nullptr, 0, nullptr, 1.f);

    // Scores -> E = exp(S) fp16 + row partial sums
    dim3 gS(Tn / 128, Tn / 128, Bn);
    tgemm<0, false, 2><<<gS, NTHR, SMEM_SZ>>>(
        qk, qk + Cn, nullptr, wt,
        Cn, QKC, QKC, Tn, QKT, QKT, TT, nullptr, nullptr, 0, zp,
        1.f / sqrtf((float)Cn));

    // join: attnV needs both scores (main) and V (side)
    cudaStreamWaitEvent(0, ss.join, 0);

    // Attn*V with per-row 1/Z normalization -> aT fp16
    dim3 gA(Cn / 128, Tn / 128, Bn);
    tgemm<0, false, 3><<<gA, NTHR, SMEM_SZ>>>(
        wt, vv, nullptr, aT,
        Tn, Tn, Tn, Cn, TT, CT, CT, nullptr, nullptr, 0, zp, 1.f);

    // Out proj + bias + residual -> out fp32
    dim3 gO(Tn / 128, Cn / 128, Bn);
    tgemm<1, true, 0><<<gO, NTHR, SMEM_SZ>>>(
        wo, aT, out, nullptr,
        Cn, Cn, Cn, Tn, 0, CT, CT, o_b, x, CT, nullptr, 1.f);
}

// round 13
// speedup vs baseline: 1.5252x; 1.5252x over previous
#include <cuda_runtime.h>
#include <cuda_fp16.h>
#include <math.h>
#include <stdint.h>

#define Bn 8
#define Cn 512
#define Tn 2048
#define CT ((size_t)Cn * Tn)
#define TT ((size_t)Tn * Tn)
#define QKC 1024                         // stacked q|k channel dim
#define QKT ((size_t)Tn * QKC)           // per-batch qk plane

typedef __half fp16;

// ---------------- scratch (static device globals; allocation-guard safe) ----
__device__ __align__(16) fp16 g_hT[Bn * Tn * Cn];    // [B,T,C] groupnormed, fp16
__device__ __align__(16) fp16 g_wqk[QKC * Cn];       // [Wq;Wk] fp16
__device__ __align__(16) fp16 g_wv[Cn * Cn];
__device__ __align__(16) fp16 g_wo[Cn * Cn];
__device__ __align__(16) float g_qkb[QKC];           // [q_b;k_b]
__device__ __align__(16) fp16 g_qk[Bn * Tn * QKC];   // [B,T,1024] q|k
__device__ __align__(16) fp16 g_vv[Bn * Cn * Tn];    // [B,C,T]
__device__ __align__(16) fp16 g_aT[Bn * Tn * Cn];    // [B,T,C]
__device__ __align__(16) fp16 g_wt[Bn * Tn * Tn];    // E = exp(scores), unnormalized
__device__ __align__(16) float g_zp[(size_t)Bn * Tn * 16];  // row-sum partials
__device__ __align__(16) float g_mean[Bn * 32];
__device__ __align__(16) float g_inv[Bn * 32];

// ---------------- PTX helpers ----------------------------------------------
__device__ __forceinline__ uint32_t s2u(const void* p) {
    uint32_t a;
    asm("{ .reg .u64 t; cvta.to.shared.u64 t, %1; cvt.u32.u64 %0, t; }"
        : "=r"(a) : "l"(p));
    return a;
}

__device__ __forceinline__ void cp16(uint32_t d, const void* s) {
    asm volatile("cp.async.cg.shared.global [%0], [%1], 16;" :: "r"(d), "l"(s) : "memory");
}

#define LDSM4(r, addr)                                                          \
    asm volatile("ldmatrix.sync.aligned.m8n8.x4.shared.b16 {%0,%1,%2,%3}, [%4];"\
        : "=r"((r)[0]), "=r"((r)[1]), "=r"((r)[2]), "=r"((r)[3]) : "r"(addr))

#define MMA16816(d, a, b0, b1)                                                  \
    asm volatile(                                                               \
        "mma.sync.aligned.m16n8k16.row.col.f32.f16.f16.f32 "                    \
        "{%0,%1,%2,%3}, {%4,%5,%6,%7}, {%8,%9}, {%0,%1,%2,%3};"                 \
        : "+f"((d)[0]), "+f"((d)[1]), "+f"((d)[2]), "+f"((d)[3])                \
        : "r"((a)[0]), "r"((a)[1]), "r"((a)[2]), "r"((a)[3]),                   \
          "r"(b0), "r"(b1))

// ---------------- GroupNorm stats -------------------------------------------
__global__ void gn_stats(const float* __restrict__ x) {
    const int bg = blockIdx.x, tid = threadIdx.x;
    const int b = bg >> 5, g = bg & 31;
    const size_t base = ((size_t)b * Cn + g * 16) * Tn;
    const float4* xv = (const float4*)(x + base);
    float s = 0.f, ss = 0.f;
    for (int i = tid; i < 8192; i += 256) {
        float4 v = xv[i];
        s += v.x + v.y + v.z + v.w;
        ss += v.x * v.x + v.y * v.y + v.z * v.z + v.w * v.w;
    }
    __shared__ float rs[256], rq[256];
    rs[tid] = s; rq[tid] = ss;
    __syncthreads();
    for (int o = 128; o > 0; o >>= 1) {
        if (tid < o) { rs[tid] += rs[tid + o]; rq[tid] += rq[tid + o]; }
        __syncthreads();
    }
    if (tid == 0) {
        float mean = rs[0] / 32768.f;
        float var = rq[0] / 32768.f - mean * mean;
        g_mean[bg] = mean;
        g_inv[bg] = rsqrtf(var + 1e-6f);
    }
}

// ---------------- GN apply + transpose -> fp16:  x[C,T] -> hT[T,C] ----------
__global__ void happly(const float* __restrict__ x, const float* __restrict__ gamma,
                       const float* __restrict__ beta) {
    __shared__ float tl[32][33];
    const int b = blockIdx.z, t0 = blockIdx.x * 32, c0 = blockIdx.y * 32;
    const int tx = threadIdx.x, ty = threadIdx.y;
#pragma unroll
    for (int k = 0; k < 4; k++) {
        int c = c0 + ty + k * 8;
        float ga = gamma[c] * g_inv[b * 32 + (c >> 4)];
        float be = beta[c] - g_mean[b * 32 + (c >> 4)] * ga;
        float v = x[((size_t)b * Cn + c) * Tn + t0 + tx];
        tl[ty + k * 8][tx] = v * ga + be;
    }
    __syncthreads();
#pragma unroll
    for (int k = 0; k < 4; k++) {
        int t = t0 + ty + k * 8;
        size_t o = ((size_t)b * Tn + t) * Cn + c0 + tx;
        g_hT[o] = __float2half_rn(tl[tx][ty + k * 8]);
    }
}

// ------- weights -> fp16 + qk bias concat, one launch -----------------------
__global__ void wconv(const float* __restrict__ qw, const float* __restrict__ kw,
                      const float* __restrict__ vw, const float* __restrict__ ow,
                      const float* __restrict__ qb, const float* __restrict__ kb) {
    const int n = Cn * Cn;
    int i = blockIdx.x * blockDim.x + threadIdx.x;
    if (i < QKC) g_qkb[i] = (i < Cn) ? qb[i] : kb[i - Cn];
    if (i >= 4 * n) return;
    int seg = i / n, j = i - seg * n;
    if (seg == 0)      g_wqk[j]     = __float2half_rn(qw[j]);
    else if (seg == 1) g_wqk[n + j] = __float2half_rn(kw[j]);
    else if (seg == 2) g_wv[j]      = __float2half_rn(vw[j]);
    else               g_wo[j]      = __float2half_rn(ow[j]);
}

#define STG_A 16384
#define STG_AB 32768
#define NSTAGE 3
#define SMEM_SZ (NSTAGE * STG_AB)   // 98304
#define NTHR 128

// ---------------- shared mainloop (inlined) ---------------------------------
// CTA tile 128x128, BK=64, 4 warps (2m x 2n), warp tile 64x64; K-major SW.
struct MainloopOut { float (*acc)[8][4]; };

__device__ __forceinline__ void run_mainloop(
    uint32_t sb, int tid, int wm, int wn,
    const char* Ap0, const char* Bp0, int S, size_t la2, size_t lb2,
    float acc[4][8][4]) {
    int lane = tid & 31;
    auto load = [&](int s, int buf) {
        size_t kb = (size_t)s << 7;
        const char* Ap = Ap0 + kb;
        const char* Bp = Bp0 + kb;
        uint32_t ab = sb + buf * STG_AB;
        uint32_t bb = ab + STG_A;
#pragma unroll
        for (int j = 0; j < 8; j++) {
            int g = tid + j * NTHR;
            int r = g >> 3, c = g & 7;
            uint32_t sw = (uint32_t)(r * 128 + ((c ^ (r & 7)) << 4));
            cp16(ab + sw, Ap + (size_t)r * la2 + c * 16);
            cp16(bb + sw, Bp + (size_t)r * lb2 + c * 16);
        }
    };

#pragma unroll
    for (int i = 0; i < 4; i++)
#pragma unroll
        for (int j = 0; j < 8; j++)
#pragma unroll
            for (int q = 0; q < 4; q++) acc[i][j][q] = 0.f;

    load(0, 0);
    asm volatile("cp.async.commit_group;");
    load(1, 1);
    asm volatile("cp.async.commit_group;");

    int cur = 0;
    for (int s = 0; s < S; s++) {
        asm volatile("cp.async.wait_group 1;");
        __syncthreads();
        if (s + 2 < S) load(s + 2, (cur + 2) % NSTAGE);
        asm volatile("cp.async.commit_group;");
        const uint32_t ab = sb + cur * STG_AB;
        const uint32_t bb = ab + STG_A;
#pragma unroll
        for (int kk = 0; kk < 4; kk++) {
            uint32_t af[4][4], bfr[4][4];
#pragma unroll
            for (int mi = 0; mi < 4; mi++) {
                int r = wm + mi * 16 + (lane & 15);
                int c = kk * 2 + (lane >> 4);
                LDSM4(af[mi], ab + r * 128 + ((c ^ (r & 7)) << 4));
            }
#pragma unroll
            for (int nj = 0; nj < 4; nj++) {
                int r = wn + nj * 16 + (lane & 7) + ((lane >> 4) << 3);
                int c = kk * 2 + ((lane >> 3) & 1);
                LDSM4(bfr[nj], bb + r * 128 + ((c ^ (r & 7)) << 4));
            }
#pragma unroll
            for (int mi = 0; mi < 4; mi++)
#pragma unroll
                for (int nj = 0; nj < 4; nj++) {
                    MMA16816(acc[mi][nj * 2 + 0], af[mi], bfr[nj][0], bfr[nj][1]);
                    MMA16816(acc[mi][nj * 2 + 1], af[mi], bfr[nj][2], bfr[nj][3]);
                }
        }
        cur = (cur + 1 == NSTAGE) ? 0 : cur + 1;
    }
}

// ---------------- fused QKV projection kernel -------------------------------
// Flat grid of 1536 CTAs: [0,1024) = QK tiles  (out qk[B,T,1024], bias over n)
//                         [1024,1536) = V tiles (out vv[B,C,T],   bias over m)
__global__ __launch_bounds__(NTHR, 2) void qkv_gemm(
    const fp16* __restrict__ hT, const fp16* __restrict__ wqk,
    const fp16* __restrict__ wv, fp16* __restrict__ qk, fp16* __restrict__ vv,
    const float* __restrict__ qkb, const float* __restrict__ vb) {
    extern __shared__ char smem[];
    const uint32_t sb = s2u(smem);
    const int tid = threadIdx.x, wid = tid >> 5, lane = tid & 31;
    const int wm = (wid >> 1) * 64, wn = (wid & 1) * 64;

    const int id = blockIdx.x;
    const bool isV = id >= 1024;
    int m0, n0, b, ldc;
    const fp16 *Ah, *Bh;
    fp16* Oh;
    size_t sA, sB, sC;
    const float* biasp;
    if (!isV) {          // QK: D[t, c_out] grid (8 n) x (16 m) x 8 b
        n0 = (id & 7) * 128;
        m0 = ((id >> 3) & 15) * 128;
        b = id >> 7;
        Ah = hT; Bh = wqk; Oh = qk;
        sA = CT; sB = 0; sC = QKT; ldc = QKC;
        biasp = qkb;
    } else {             // V: D[c_out, t] grid (16 n) x (4 m) x 8 b
        int id2 = id - 1024;
        n0 = (id2 & 15) * 128;
        m0 = ((id2 >> 4) & 3) * 128;
        b = id2 >> 6;
        Ah = wv; Bh = hT; Oh = vv;
        sA = 0; sB = CT; sC = CT; ldc = Tn;
        biasp = vb;
    }

    const char* Ap0 = (const char*)(Ah + (size_t)b * sA + (size_t)m0 * Cn);
    const char* Bp0 = (const char*)(Bh + (size_t)b * sB + (size_t)n0 * Cn);

    float acc[4][8][4];
    run_mainloop(sb, tid, wm, wn, Ap0, Bp0, Cn >> 6, Cn * 2, Cn * 2, acc);

    const int qr = lane >> 2, qc = (lane & 3) * 2;
#pragma unroll
    for (int mi = 0; mi < 4; mi++) {
#pragma unroll
        for (int ni = 0; ni < 8; ni++) {
            const int mA = m0 + wm + mi * 16 + qr;
            const int nA = n0 + wn + ni * 8 + qc;
#pragma unroll
            for (int h = 0; h < 2; h++) {
                const int m = mA + h * 8;
                float v0 = acc[mi][ni][h * 2 + 0];
                float v1 = acc[mi][ni][h * 2 + 1];
                if (isV) { float bv = biasp[m]; v0 += bv; v1 += bv; }
                else     { v0 += biasp[nA]; v1 += biasp[nA + 1]; }
                __align__(4) fp16 ph[2] = {__float2half_rn(v0), __float2half_rn(v1)};
                *(uint32_t*)(Oh + (size_t)b * sC + (size_t)m * ldc + nA) = *(uint32_t*)ph;
            }
        }
    }
}

// ---------------- general GEMM (scores / attnV / out-proj) ------------------
// OUT_MODE: 0 = fp32 + residual, 2 = fp16 exp + Z partials, 3 = 1/Z scaled fp16
template <int BIAS_MODE, bool HAS_RES, int OUT_MODE>
__global__ __launch_bounds__(NTHR, 2) void tgemm(
    const fp16* __restrict__ Ah, const fp16* __restrict__ Bh,
    float* __restrict__ Cf, fp16* __restrict__ Oh,
    int K, int lda, int ldb, int ldc,
    size_t sA, size_t sB, size_t sC,
    const float* __restrict__ bias, const float* __restrict__ res, size_t sRes,
    float* __restrict__ zp, float scale) {
    extern __shared__ char smem[];
    const uint32_t sb = s2u(smem);
    const int tid = threadIdx.x, wid = tid >> 5, lane = tid & 31;
    const int m0 = blockIdx.y * 128, n0 = blockIdx.x * 128, b = blockIdx.z;
    const int wm = (wid >> 1) * 64, wn = (wid & 1) * 64;

    const char* Ap0 = (const char*)(Ah + (size_t)b * sA + (size_t)m0 * lda);
    const char* Bp0 = (const char*)(Bh + (size_t)b * sB + (size_t)n0 * ldb);

    float acc[4][8][4];
    run_mainloop(sb, tid, wm, wn, Ap0, Bp0, K >> 6,
                 (size_t)lda * 2, (size_t)ldb * 2, acc);

    const int qr = lane >> 2, qc = (lane & 3) * 2;

    float rz[4][2];
    if (OUT_MODE == 3) {
#pragma unroll
        for (int mi = 0; mi < 4; mi++)
#pragma unroll
            for (int h = 0; h < 2; h++) {
                int m = m0 + wm + mi * 16 + h * 8 + qr;
                const float4* z4 = (const float4*)(zp + ((size_t)b * Tn + m) * 16);
                float4 a = z4[0], b4 = z4[1], c4 = z4[2], d4 = z4[3];
                float z = (a.x + a.y + a.z + a.w) + (b4.x + b4.y + b4.z + b4.w) +
                          (c4.x + c4.y + c4.z + c4.w) + (d4.x + d4.y + d4.z + d4.w);
                rz[mi][h] = 1.f / z;
            }
    }

    float rsum[4][2];
    if (OUT_MODE == 2) {
#pragma unroll
        for (int mi = 0; mi < 4; mi++)
#pragma unroll
            for (int h = 0; h < 2; h++) rsum[mi][h] = 0.f;
    }

#pragma unroll
    for (int mi = 0; mi < 4; mi++) {
#pragma unroll
        for (int ni = 0; ni < 8; ni++) {
            const int mA = m0 + wm + mi * 16 + qr;
            const int nA = n0 + wn + ni * 8 + qc;
#pragma unroll
            for (int h = 0; h < 2; h++) {
                const int m = mA + h * 8;
                float v0 = acc[mi][ni][h * 2 + 0] * scale;
                float v1 = acc[mi][ni][h * 2 + 1] * scale;
                if (BIAS_MODE == 1) { float bv = bias[m]; v0 += bv; v1 += bv; }
                const size_t go = (size_t)m * ldc + nA;
                if (OUT_MODE == 2) {
                    v0 = __expf(v0);
                    v1 = __expf(v1);
                    rsum[mi][h] += v0 + v1;
                    __align__(4) fp16 ph[2] = {__float2half_rn(v0), __float2half_rn(v1)};
                    *(uint32_t*)(Oh + (size_t)b * sC + go) = *(uint32_t*)ph;
                } else if (OUT_MODE == 3) {
                    v0 *= rz[mi][h];
                    v1 *= rz[mi][h];
                    __align__(4) fp16 ph[2] = {__float2half_rn(v0), __float2half_rn(v1)};
                    *(uint32_t*)(Oh + (size_t)b * sC + go) = *(uint32_t*)ph;
                } else {
                    if (HAS_RES) {
                        float2 r2 = *(const float2*)(res + (size_t)b * sRes + go);
                        v0 += r2.x; v1 += r2.y;
                    }
                    float2 o2 = {v0, v1};
                    *(float2*)(Cf + (size_t)b * sC + go) = o2;
                }
            }
        }
    }

    if (OUT_MODE == 2) {
#pragma unroll
        for (int mi = 0; mi < 4; mi++)
#pragma unroll
            for (int h = 0; h < 2; h++) {
                float v = rsum[mi][h];
                v += __shfl_xor_sync(0xffffffffu, v, 1);
                v += __shfl_xor_sync(0xffffffffu, v, 2);
                rsum[mi][h] = v;
            }
        __syncthreads();
        float* zsm = (float*)smem;  // [128][2]
        if ((lane & 3) == 0) {
#pragma unroll
            for (int mi = 0; mi < 4; mi++)
#pragma unroll
                for (int h = 0; h < 2; h++) {
                    int r = wm + mi * 16 + h * 8 + qr;
                    zsm[r * 2 + (wid & 1)] = rsum[mi][h];
                }
        }
        __syncthreads();
        float z = zsm[tid * 2] + zsm[tid * 2 + 1];
        zp[((size_t)b * Tn + m0 + tid) * 16 + blockIdx.x] = z;
    }
}

// ---------------- launch ----------------------------------------------------
template <typename T>
static T* sym_base(const void* sym) {
    void* p = nullptr;
    cudaGetSymbolAddress(&p, sym);
    return (T*)p;
}

extern "C" void kernel_launch(void* const* d_in, const int* in_sizes, int n_in,
                              void* d_out, int out_size) {
    const float* x = (const float*)d_in[0];
    const float* gamma = (const float*)d_in[1];
    const float* beta = (const float*)d_in[2];
    const float* q_w = (const float*)d_in[3];
    const float* q_b = (const float*)d_in[4];
    const float* k_w = (const float*)d_in[5];
    const float* k_b = (const float*)d_in[6];
    const float* v_w = (const float*)d_in[7];
    const float* v_b = (const float*)d_in[8];
    const float* o_w = (const float*)d_in[9];
    const float* o_b = (const float*)d_in[10];
    float* out = (float*)d_out;

    cudaFuncSetAttribute(qkv_gemm, cudaFuncAttributeMaxDynamicSharedMemorySize, SMEM_SZ);
    cudaFuncSetAttribute(tgemm<0, false, 2>, cudaFuncAttributeMaxDynamicSharedMemorySize, SMEM_SZ);
    cudaFuncSetAttribute(tgemm<0, false, 3>, cudaFuncAttributeMaxDynamicSharedMemorySize, SMEM_SZ);
    cudaFuncSetAttribute(tgemm<1, true, 0>, cudaFuncAttributeMaxDynamicSharedMemorySize, SMEM_SZ);

    fp16* hT = sym_base<fp16>(g_hT);
    fp16* wqk = sym_base<fp16>(g_wqk);
    fp16* wv = sym_base<fp16>(g_wv);
    fp16* wo = sym_base<fp16>(g_wo);
    fp16* qk = sym_base<fp16>(g_qk);
    fp16* vv = sym_base<fp16>(g_vv);
    fp16* aT = sym_base<fp16>(g_aT);
    fp16* wt = sym_base<fp16>(g_wt);
    float* zp = sym_base<float>(g_zp);
    float* qkb = sym_base<float>(g_qkb);

    // 0-2: GN stats, GN apply+transpose, weights convert
    wconv<<<(4 * Cn * Cn + 255) / 256, 256>>>(q_w, k_w, v_w, o_w, q_b, k_b);
    gn_stats<<<Bn * 32, 256>>>(x);
    happly<<<dim3(Tn / 32, Cn / 32, Bn), dim3(32, 8)>>>(x, gamma, beta);

    // 3: fused Q|K + V projections, one 1536-CTA launch
    qkv_gemm<<<1536, NTHR, SMEM_SZ>>>(hT, wqk, wv, qk, vv, qkb, v_b);

    // 4: Scores -> E = exp(S) fp16 + row partial sums
    dim3 gS(Tn / 128, Tn / 128, Bn);
    tgemm<0, false, 2><<<gS, NTHR, SMEM_SZ>>>(
        qk, qk + Cn, nullptr, wt,
        Cn, QKC, QKC, Tn, QKT, QKT, TT, nullptr, nullptr, 0, zp,
        1.f / sqrtf((float)Cn));

    // 5: Attn*V with per-row 1/Z normalization -> aT fp16
    dim3 gA(Cn / 128, Tn / 128, Bn);
    tgemm<0, false, 3><<<gA, NTHR, SMEM_SZ>>>(
        wt, vv, nullptr, aT,
        Tn, Tn, Tn, Cn, TT, CT, CT, nullptr, nullptr, 0, zp, 1.f);

    // 6: Out proj + bias + residual -> out fp32
    dim3 gO(Tn / 128, Cn / 128, Bn);
    tgemm<1, true, 0><<<gO, NTHR, SMEM_SZ>>>(
        wo, aT, out, nullptr,
        Cn, Cn, Cn, Tn, 0, CT, CT, o_b, x, CT, nullptr, 1.f);
}

// round 15
// speedup vs baseline: 1.5727x; 1.0312x over previous
#include <cuda_runtime.h>
#include <cuda_fp16.h>
#include <math.h>
#include <stdint.h>

#define Bn 8
#define Cn 512
#define Tn 2048
#define CT ((size_t)Cn * Tn)
#define TT ((size_t)Tn * Tn)
#define QKC 1024                         // stacked q|k channel dim
#define QKT ((size_t)Tn * QKC)           // per-batch qk plane

typedef __half fp16;

// ---------------- scratch (static device globals; allocation-guard safe) ----
__device__ __align__(16) fp16 g_hT[Bn * Tn * Cn];    // [B,T,C] groupnormed, fp16
__device__ __align__(16) fp16 g_wqk[QKC * Cn];       // [Wq;Wk] fp16
__device__ __align__(16) fp16 g_wv[Cn * Cn];
__device__ __align__(16) fp16 g_wo[Cn * Cn];
__device__ __align__(16) float g_qkb[QKC];           // [q_b;k_b]
__device__ __align__(16) fp16 g_qk[Bn * Tn * QKC];   // [B,T,1024] q|k
__device__ __align__(16) fp16 g_vv[Bn * Cn * Tn];    // [B,C,T]
__device__ __align__(16) fp16 g_aT[Bn * Tn * Cn];    // [B,T,C]
__device__ __align__(16) fp16 g_wt[Bn * Tn * Tn];    // E = exp(scores), unnormalized
__device__ __align__(16) float g_zp[(size_t)Bn * Tn * 16];  // row-sum partials
__device__ __align__(16) float g_mean[Bn * 32];
__device__ __align__(16) float g_inv[Bn * 32];

// ---------------- PTX helpers ----------------------------------------------
__device__ __forceinline__ uint32_t s2u(const void* p) {
    uint32_t a;
    asm("{ .reg .u64 t; cvta.to.shared.u64 t, %1; cvt.u32.u64 %0, t; }"
        : "=r"(a) : "l"(p));
    return a;
}

__device__ __forceinline__ void cp16(uint32_t d, const void* s) {
    asm volatile("cp.async.cg.shared.global [%0], [%1], 16;" :: "r"(d), "l"(s) : "memory");
}

#define LDSM4(r, addr)                                                          \
    asm volatile("ldmatrix.sync.aligned.m8n8.x4.shared.b16 {%0,%1,%2,%3}, [%4];"\
        : "=r"((r)[0]), "=r"((r)[1]), "=r"((r)[2]), "=r"((r)[3]) : "r"(addr))

#define MMA16816(d, a, b0, b1)                                                  \
    asm volatile(                                                               \
        "mma.sync.aligned.m16n8k16.row.col.f32.f16.f16.f32 "                    \
        "{%0,%1,%2,%3}, {%4,%5,%6,%7}, {%8,%9}, {%0,%1,%2,%3};"                 \
        : "+f"((d)[0]), "+f"((d)[1]), "+f"((d)[2]), "+f"((d)[3])                \
        : "r"((a)[0]), "r"((a)[1]), "r"((a)[2]), "r"((a)[3]),                   \
          "r"(b0), "r"(b1))

// ---------------- prep: weight convert + GN stats, one launch ---------------
// blocks [0, 4096): wconv (4096 blk x 256 thr = 4*Cn*Cn elems)
// blocks [4096, 4096+256): gn_stats (one per (b, group))
#define WCONV_BLKS 4096
__global__ void prep(const float* __restrict__ qw, const float* __restrict__ kw,
                     const float* __restrict__ vw, const float* __restrict__ ow,
                     const float* __restrict__ qb, const float* __restrict__ kb,
                     const float* __restrict__ x) {
    const int n = Cn * Cn;
    if (blockIdx.x < WCONV_BLKS) {
        int i = blockIdx.x * blockDim.x + threadIdx.x;
        if (i < QKC) g_qkb[i] = (i < Cn) ? qb[i] : kb[i - Cn];
        int seg = i / n, j = i - seg * n;
        if (seg == 0)      g_wqk[j]     = __float2half_rn(qw[j]);
        else if (seg == 1) g_wqk[n + j] = __float2half_rn(kw[j]);
        else if (seg == 2) g_wv[j]      = __float2half_rn(vw[j]);
        else               g_wo[j]      = __float2half_rn(ow[j]);
        return;
    }
    const int bg = blockIdx.x - WCONV_BLKS, tid = threadIdx.x;
    const int b = bg >> 5, g = bg & 31;
    const size_t base = ((size_t)b * Cn + g * 16) * Tn;
    const float4* xv = (const float4*)(x + base);
    float s = 0.f, ss = 0.f;
    for (int i = tid; i < 8192; i += 256) {
        float4 v = xv[i];
        s += v.x + v.y + v.z + v.w;
        ss += v.x * v.x + v.y * v.y + v.z * v.z + v.w * v.w;
    }
    __shared__ float rs[256], rq[256];
    rs[tid] = s; rq[tid] = ss;
    __syncthreads();
    for (int o = 128; o > 0; o >>= 1) {
        if (tid < o) { rs[tid] += rs[tid + o]; rq[tid] += rq[tid + o]; }
        __syncthreads();
    }
    if (tid == 0) {
        float mean = rs[0] / 32768.f;
        float var = rq[0] / 32768.f - mean * mean;
        g_mean[bg] = mean;
        g_inv[bg] = rsqrtf(var + 1e-6f);
    }
}

// ---------------- GN apply + transpose -> fp16:  x[C,T] -> hT[T,C] ----------
// 32t x 64c tiles; fp16 pair (uint32) stores.
__global__ void happly(const float* __restrict__ x, const float* __restrict__ gamma,
                       const float* __restrict__ beta) {
    __shared__ float tl[64][33];
    const int b = blockIdx.z, t0 = blockIdx.x * 32, c0 = blockIdx.y * 64;
    const int tx = threadIdx.x, ty = threadIdx.y;
#pragma unroll
    for (int k = 0; k < 8; k++) {
        int cl = ty + k * 8;
        int c = c0 + cl;
        float ga = gamma[c] * g_inv[b * 32 + (c >> 4)];
        float be = beta[c] - g_mean[b * 32 + (c >> 4)] * ga;
        float v = x[((size_t)b * Cn + c) * Tn + t0 + tx];
        tl[cl][tx] = v * ga + be;
    }
    __syncthreads();
#pragma unroll
    for (int k = 0; k < 4; k++) {
        int t = t0 + ty + k * 8;
        __align__(4) fp16 p[2] = {
            __float2half_rn(tl[tx * 2 + 0][ty + k * 8]),
            __float2half_rn(tl[tx * 2 + 1][ty + k * 8])};
        size_t o = ((size_t)b * Tn + t) * Cn + c0 + tx * 2;
        *(uint32_t*)(g_hT + o) = *(uint32_t*)p;
    }
}

#define STG_A 16384
#define STG_AB 32768
#define NSTAGE 3
#define SMEM_SZ (NSTAGE * STG_AB)   // 98304
#define NTHR 128

// ---------------- shared mainloop (inlined) ---------------------------------
// CTA tile 128x128, BK=64, 4 warps (2m x 2n), warp tile 64x64; K-major SW.
// cp.async issue for stage s+2 spread across the 4 kk subtiles.
__device__ __forceinline__ void run_mainloop(
    uint32_t sb, int tid, int wm, int wn,
    const char* Ap0, const char* Bp0, int S, size_t la2, size_t lb2,
    float acc[4][8][4]) {
    int lane = tid & 31;
    auto load_part = [&](int s, int buf, int part) {  // part in [0,4): 2 pairs each
        size_t kb = (size_t)s << 7;
        const char* Ap = Ap0 + kb;
        const char* Bp = Bp0 + kb;
        uint32_t ab = sb + buf * STG_AB;
        uint32_t bb = ab + STG_A;
#pragma unroll
        for (int j = part * 2; j < part * 2 + 2; j++) {
            int g = tid + j * NTHR;
            int r = g >> 3, c = g & 7;
            uint32_t sw = (uint32_t)(r * 128 + ((c ^ (r & 7)) << 4));
            cp16(ab + sw, Ap + (size_t)r * la2 + c * 16);
            cp16(bb + sw, Bp + (size_t)r * lb2 + c * 16);
        }
    };
    auto load_all = [&](int s, int buf) {
#pragma unroll
        for (int p = 0; p < 4; p++) load_part(s, buf, p);
    };

#pragma unroll
    for (int i = 0; i < 4; i++)
#pragma unroll
        for (int j = 0; j < 8; j++)
#pragma unroll
            for (int q = 0; q < 4; q++) acc[i][j][q] = 0.f;

    load_all(0, 0);
    asm volatile("cp.async.commit_group;");
    load_all(1, 1);
    asm volatile("cp.async.commit_group;");

    int cur = 0;
    for (int s = 0; s < S; s++) {
        asm volatile("cp.async.wait_group 1;");
        __syncthreads();
        const bool pf = (s + 2 < S);
        const int nb = (cur + 2) % NSTAGE;
        const uint32_t ab = sb + cur * STG_AB;
        const uint32_t bb = ab + STG_A;
#pragma unroll
        for (int kk = 0; kk < 4; kk++) {
            uint32_t af[4][4], bfr[4][4];
#pragma unroll
            for (int mi = 0; mi < 4; mi++) {
                int r = wm + mi * 16 + (lane & 15);
                int c = kk * 2 + (lane >> 4);
                LDSM4(af[mi], ab + r * 128 + ((c ^ (r & 7)) << 4));
            }
#pragma unroll
            for (int nj = 0; nj < 4; nj++) {
                int r = wn + nj * 16 + (lane & 7) + ((lane >> 4) << 3);
                int c = kk * 2 + ((lane >> 3) & 1);
                LDSM4(bfr[nj], bb + r * 128 + ((c ^ (r & 7)) << 4));
            }
            if (pf) load_part(s + 2, nb, kk);
#pragma unroll
            for (int mi = 0; mi < 4; mi++)
#pragma unroll
                for (int nj = 0; nj < 4; nj++) {
                    MMA16816(acc[mi][nj * 2 + 0], af[mi], bfr[nj][0], bfr[nj][1]);
                    MMA16816(acc[mi][nj * 2 + 1], af[mi], bfr[nj][2], bfr[nj][3]);
                }
        }
        asm volatile("cp.async.commit_group;");
        cur = (cur + 1 == NSTAGE) ? 0 : cur + 1;
    }
}

// ---------------- fused QKV projection kernel -------------------------------
// Flat grid of 1536 CTAs: [0,1024) = QK tiles  (out qk[B,T,1024], bias over n)
//                         [1024,1536) = V tiles (out vv[B,C,T],   bias over m)
__global__ __launch_bounds__(NTHR, 2) void qkv_gemm(
    const fp16* __restrict__ hT, const fp16* __restrict__ wqk,
    const fp16* __restrict__ wv, fp16* __restrict__ qk, fp16* __restrict__ vv,
    const float* __restrict__ qkb, const float* __restrict__ vb) {
    extern __shared__ char smem[];
    const uint32_t sb = s2u(smem);
    const int tid = threadIdx.x, wid = tid >> 5, lane = tid & 31;
    const int wm = (wid >> 1) * 64, wn = (wid & 1) * 64;

    const int id = blockIdx.x;
    const bool isV = id >= 1024;
    int m0, n0, b, ldc;
    const fp16 *Ah, *Bh;
    fp16* Oh;
    size_t sA, sB, sC;
    const float* biasp;
    if (!isV) {          // QK: D[t, c_out]
        n0 = (id & 7) * 128;
        m0 = ((id >> 3) & 15) * 128;
        b = id >> 7;
        Ah = hT; Bh = wqk; Oh = qk;
        sA = CT; sB = 0; sC = QKT; ldc = QKC;
        biasp = qkb;
    } else {             // V: D[c_out, t]
        int id2 = id - 1024;
        n0 = (id2 & 15) * 128;
        m0 = ((id2 >> 4) & 3) * 128;
        b = id2 >> 6;
        Ah = wv; Bh = hT; Oh = vv;
        sA = 0; sB = CT; sC = CT; ldc = Tn;
        biasp = vb;
    }

    const char* Ap0 = (const char*)(Ah + (size_t)b * sA + (size_t)m0 * Cn);
    const char* Bp0 = (const char*)(Bh + (size_t)b * sB + (size_t)n0 * Cn);

    float acc[4][8][4];
    run_mainloop(sb, tid, wm, wn, Ap0, Bp0, Cn >> 6, Cn * 2, Cn * 2, acc);

    const int qr = lane >> 2, qc = (lane & 3) * 2;
#pragma unroll
    for (int mi = 0; mi < 4; mi++) {
#pragma unroll
        for (int ni = 0; ni < 8; ni++) {
            const int mA = m0 + wm + mi * 16 + qr;
            const int nA = n0 + wn + ni * 8 + qc;
#pragma unroll
            for (int h = 0; h < 2; h++) {
                const int m = mA + h * 8;
                float v0 = acc[mi][ni][h * 2 + 0];
                float v1 = acc[mi][ni][h * 2 + 1];
                if (isV) { float bv = biasp[m]; v0 += bv; v1 += bv; }
                else     { v0 += biasp[nA]; v1 += biasp[nA + 1]; }
                __align__(4) fp16 ph[2] = {__float2half_rn(v0), __float2half_rn(v1)};
                *(uint32_t*)(Oh + (size_t)b * sC + (size_t)m * ldc + nA) = *(uint32_t*)ph;
            }
        }
    }
}

// ---------------- general GEMM (scores / attnV / out-proj) ------------------
// OUT_MODE: 0 = fp32 + residual, 2 = fp16 exp + Z partials, 3 = 1/Z scaled fp16
template <int BIAS_MODE, bool HAS_RES, int OUT_MODE>
__global__ __launch_bounds__(NTHR, 2) void tgemm(
    const fp16* __restrict__ Ah, const fp16* __restrict__ Bh,
    float* __restrict__ Cf, fp16* __restrict__ Oh,
    int K, int lda, int ldb, int ldc,
    size_t sA, size_t sB, size_t sC,
    const float* __restrict__ bias, const float* __restrict__ res, size_t sRes,
    float* __restrict__ zp, float scale) {
    extern __shared__ char smem[];
    const uint32_t sb = s2u(smem);
    const int tid = threadIdx.x, wid = tid >> 5, lane = tid & 31;
    const int m0 = blockIdx.y * 128, n0 = blockIdx.x * 128, b = blockIdx.z;
    const int wm = (wid >> 1) * 64, wn = (wid & 1) * 64;

    const char* Ap0 = (const char*)(Ah + (size_t)b * sA + (size_t)m0 * lda);
    const char* Bp0 = (const char*)(Bh + (size_t)b * sB + (size_t)n0 * ldb);

    float acc[4][8][4];
    run_mainloop(sb, tid, wm, wn, Ap0, Bp0, K >> 6,
                 (size_t)lda * 2, (size_t)ldb * 2, acc);

    const int qr = lane >> 2, qc = (lane & 3) * 2;

    float rz[4][2];
    if (OUT_MODE == 3) {
#pragma unroll
        for (int mi = 0; mi < 4; mi++)
#pragma unroll
            for (int h = 0; h < 2; h++) {
                int m = m0 + wm + mi * 16 + h * 8 + qr;
                const float4* z4 = (const float4*)(zp + ((size_t)b * Tn + m) * 16);
                float4 a = z4[0], b4 = z4[1], c4 = z4[2], d4 = z4[3];
                float z = (a.x + a.y + a.z + a.w) + (b4.x + b4.y + b4.z + b4.w) +
                          (c4.x + c4.y + c4.z + c4.w) + (d4.x + d4.y + d4.z + d4.w);
                rz[mi][h] = 1.f / z;
            }
    }

    float rsum[4][2];
    if (OUT_MODE == 2) {
#pragma unroll
        for (int mi = 0; mi < 4; mi++)
#pragma unroll
            for (int h = 0; h < 2; h++) rsum[mi][h] = 0.f;
    }

#pragma unroll
    for (int mi = 0; mi < 4; mi++) {
#pragma unroll
        for (int ni = 0; ni < 8; ni++) {
            const int mA = m0 + wm + mi * 16 + qr;
            const int nA = n0 + wn + ni * 8 + qc;
#pragma unroll
            for (int h = 0; h < 2; h++) {
                const int m = mA + h * 8;
                float v0 = acc[mi][ni][h * 2 + 0] * scale;
                float v1 = acc[mi][ni][h * 2 + 1] * scale;
                if (BIAS_MODE == 1) { float bv = bias[m]; v0 += bv; v1 += bv; }
                const size_t go = (size_t)m * ldc + nA;
                if (OUT_MODE == 2) {
                    v0 = __expf(v0);
                    v1 = __expf(v1);
                    rsum[mi][h] += v0 + v1;
                    __align__(4) fp16 ph[2] = {__float2half_rn(v0), __float2half_rn(v1)};
                    *(uint32_t*)(Oh + (size_t)b * sC + go) = *(uint32_t*)ph;
                } else if (OUT_MODE == 3) {
                    v0 *= rz[mi][h];
                    v1 *= rz[mi][h];
                    __align__(4) fp16 ph[2] = {__float2half_rn(v0), __float2half_rn(v1)};
                    *(uint32_t*)(Oh + (size_t)b * sC + go) = *(uint32_t*)ph;
                } else {
                    if (HAS_RES) {
                        float2 r2 = *(const float2*)(res + (size_t)b * sRes + go);
                        v0 += r2.x; v1 += r2.y;
                    }
                    float2 o2 = {v0, v1};
                    *(float2*)(Cf + (size_t)b * sC + go) = o2;
                }
            }
        }
    }

    if (OUT_MODE == 2) {
#pragma unroll
        for (int mi = 0; mi < 4; mi++)
#pragma unroll
            for (int h = 0; h < 2; h++) {
                float v = rsum[mi][h];
                v += __shfl_xor_sync(0xffffffffu, v, 1);
                v += __shfl_xor_sync(0xffffffffu, v, 2);
                rsum[mi][h] = v;
            }
        __syncthreads();
        float* zsm = (float*)smem;  // [128][2]
        if ((lane & 3) == 0) {
#pragma unroll
            for (int mi = 0; mi < 4; mi++)
#pragma unroll
                for (int h = 0; h < 2; h++) {
                    int r = wm + mi * 16 + h * 8 + qr;
                    zsm[r * 2 + (wid & 1)] = rsum[mi][h];
                }
        }
        __syncthreads();
        float z = zsm[tid * 2] + zsm[tid * 2 + 1];
        zp[((size_t)b * Tn + m0 + tid) * 16 + blockIdx.x] = z;
    }
}

// ---------------- launch ----------------------------------------------------
template <typename T>
static T* sym_base(const void* sym) {
    void* p = nullptr;
    cudaGetSymbolAddress(&p, sym);
    return (T*)p;
}

extern "C" void kernel_launch(void* const* d_in, const int* in_sizes, int n_in,
                              void* d_out, int out_size) {
    const float* x = (const float*)d_in[0];
    const float* gamma = (const float*)d_in[1];
    const float* beta = (const float*)d_in[2];
    const float* q_w = (const float*)d_in[3];
    const float* q_b = (const float*)d_in[4];
    const float* k_w = (const float*)d_in[5];
    const float* k_b = (const float*)d_in[6];
    const float* v_w = (const float*)d_in[7];
    const float* v_b = (const float*)d_in[8];
    const float* o_w = (const float*)d_in[9];
    const float* o_b = (const float*)d_in[10];
    float* out = (float*)d_out;

    cudaFuncSetAttribute(qkv_gemm, cudaFuncAttributeMaxDynamicSharedMemorySize, SMEM_SZ);
    cudaFuncSetAttribute(tgemm<0, false, 2>, cudaFuncAttributeMaxDynamicSharedMemorySize, SMEM_SZ);
    cudaFuncSetAttribute(tgemm<0, false, 3>, cudaFuncAttributeMaxDynamicSharedMemorySize, SMEM_SZ);
    cudaFuncSetAttribute(tgemm<1, true, 0>, cudaFuncAttributeMaxDynamicSharedMemorySize, SMEM_SZ);

    fp16* hT = sym_base<fp16>(g_hT);
    fp16* wqk = sym_base<fp16>(g_wqk);
    fp16* wv = sym_base<fp16>(g_wv);
    fp16* wo = sym_base<fp16>(g_wo);
    fp16* qk = sym_base<fp16>(g_qk);
    fp16* vv = sym_base<fp16>(g_vv);
    fp16* aT = sym_base<fp16>(g_aT);
    fp16* wt = sym_base<fp16>(g_wt);
    float* zp = sym_base<float>(g_zp);
    float* qkb = sym_base<float>(g_qkb);

    // 0: weights convert + GN stats (fused)  1: GN apply+transpose
    prep<<<WCONV_BLKS + Bn * 32, 256>>>(q_w, k_w, v_w, o_w, q_b, k_b, x);
    happly<<<dim3(Tn / 32, Cn / 64, Bn), dim3(32, 8)>>>(x, gamma, beta);

    // 2: fused Q|K + V projections, one 1536-CTA launch
    qkv_gemm<<<1536, NTHR, SMEM_SZ>>>(hT, wqk, wv, qk, vv, qkb, v_b);

    // 3: Scores -> E = exp(S) fp16 + row partial sums
    dim3 gS(Tn / 128, Tn / 128, Bn);
    tgemm<0, false, 2><<<gS, NTHR, SMEM_SZ>>>(
        qk, qk + Cn, nullptr, wt,
        Cn, QKC, QKC, Tn, QKT, QKT, TT, nullptr, nullptr, 0, zp,
        1.f / sqrtf((float)Cn));

    // 4: Attn*V with per-row 1/Z normalization -> aT fp16
    dim3 gA(Cn / 128, Tn / 128, Bn);
    tgemm<0, false, 3><<<gA, NTHR, SMEM_SZ>>>(
        wt, vv, nullptr, aT,
        Tn, Tn, Tn, Cn, TT, CT, CT, nullptr, nullptr, 0, zp, 1.f);

    // 5: Out proj + bias + residual -> out fp32
    dim3 gO(Tn / 128, Cn / 128, Bn);
    tgemm<1, true, 0><<<gO, NTHR, SMEM_SZ>>>(
        wo, aT, out, nullptr,
        Cn, Cn, Cn, Tn, 0, CT, CT, o_b, x, CT, nullptr, 1.f);
}

// round 16
// speedup vs baseline: 1.5871x; 1.0092x over previous
#include <cuda_runtime.h>
#include <cuda_fp16.h>
#include <math.h>
#include <stdint.h>

#define Bn 8
#define Cn 512
#define Tn 2048
#define CT ((size_t)Cn * Tn)
#define TT ((size_t)Tn * Tn)
#define QKC 1024                         // stacked q|k channel dim
#define QKT ((size_t)Tn * QKC)           // per-batch qk plane

typedef __half fp16;

// ---------------- scratch (static device globals; allocation-guard safe) ----
__device__ __align__(16) fp16 g_hT[Bn * Tn * Cn];    // [B,T,C] groupnormed, fp16
__device__ __align__(16) fp16 g_wqk[QKC * Cn];       // [Wq;Wk] fp16
__device__ __align__(16) fp16 g_wv[Cn * Cn];
__device__ __align__(16) fp16 g_wo[Cn * Cn];
__device__ __align__(16) float g_qkb[QKC];           // [q_b;k_b]
__device__ __align__(16) fp16 g_qk[Bn * Tn * QKC];   // [B,T,1024] q|k
__device__ __align__(16) fp16 g_vv[Bn * Cn * Tn];    // [B,C,T]
__device__ __align__(16) fp16 g_aT[Bn * Tn * Cn];    // [B,T,C]
__device__ __align__(16) fp16 g_wt[Bn * Tn * Tn];    // E = exp(scores), unnormalized
__device__ __align__(16) float g_zp[(size_t)Bn * Tn * 16];  // row-sum partials
__device__ __align__(16) float g_mean[Bn * 32];
__device__ __align__(16) float g_inv[Bn * 32];

// ---------------- PTX helpers ----------------------------------------------
__device__ __forceinline__ uint32_t s2u(const void* p) {
    uint32_t a;
    asm("{ .reg .u64 t; cvta.to.shared.u64 t, %1; cvt.u32.u64 %0, t; }"
        : "=r"(a) : "l"(p));
    return a;
}

__device__ __forceinline__ void cp16(uint32_t d, const void* s) {
    asm volatile("cp.async.cg.shared.global [%0], [%1], 16;" :: "r"(d), "l"(s) : "memory");
}

#define LDSM4(r, addr)                                                          \
    asm volatile("ldmatrix.sync.aligned.m8n8.x4.shared.b16 {%0,%1,%2,%3}, [%4];"\
        : "=r"((r)[0]), "=r"((r)[1]), "=r"((r)[2]), "=r"((r)[3]) : "r"(addr))

#define MMA16816(d, a, b0, b1)                                                  \
    asm volatile(                                                               \
        "mma.sync.aligned.m16n8k16.row.col.f32.f16.f16.f32 "                    \
        "{%0,%1,%2,%3}, {%4,%5,%6,%7}, {%8,%9}, {%0,%1,%2,%3};"                 \
        : "+f"((d)[0]), "+f"((d)[1]), "+f"((d)[2]), "+f"((d)[3])                \
        : "r"((a)[0]), "r"((a)[1]), "r"((a)[2]), "r"((a)[3]),                   \
          "r"(b0), "r"(b1))

// ---------------- prep: weight convert + GN stats, one launch ---------------
#define WCONV_BLKS 4096
__global__ void prep(const float* __restrict__ qw, const float* __restrict__ kw,
                     const float* __restrict__ vw, const float* __restrict__ ow,
                     const float* __restrict__ qb, const float* __restrict__ kb,
                     const float* __restrict__ x) {
    const int n = Cn * Cn;
    if (blockIdx.x < WCONV_BLKS) {
        int i = blockIdx.x * blockDim.x + threadIdx.x;
        if (i < QKC) g_qkb[i] = (i < Cn) ? qb[i] : kb[i - Cn];
        int seg = i / n, j = i - seg * n;
        if (seg == 0)      g_wqk[j]     = __float2half_rn(qw[j]);
        else if (seg == 1) g_wqk[n + j] = __float2half_rn(kw[j]);
        else if (seg == 2) g_wv[j]      = __float2half_rn(vw[j]);
        else               g_wo[j]      = __float2half_rn(ow[j]);
        return;
    }
    const int bg = blockIdx.x - WCONV_BLKS, tid = threadIdx.x;
    const int b = bg >> 5, g = bg & 31;
    const size_t base = ((size_t)b * Cn + g * 16) * Tn;
    const float4* xv = (const float4*)(x + base);
    float s = 0.f, ss = 0.f;
    for (int i = tid; i < 8192; i += 256) {
        float4 v = xv[i];
        s += v.x + v.y + v.z + v.w;
        ss += v.x * v.x + v.y * v.y + v.z * v.z + v.w * v.w;
    }
    __shared__ float rs[256], rq[256];
    rs[tid] = s; rq[tid] = ss;
    __syncthreads();
    for (int o = 128; o > 0; o >>= 1) {
        if (tid < o) { rs[tid] += rs[tid + o]; rq[tid] += rq[tid + o]; }
        __syncthreads();
    }
    if (tid == 0) {
        float mean = rs[0] / 32768.f;
        float var = rq[0] / 32768.f - mean * mean;
        g_mean[bg] = mean;
        g_inv[bg] = rsqrtf(var + 1e-6f);
    }
}

// ---------------- GN apply + transpose -> fp16:  x[C,T] -> hT[T,C] ----------
__global__ void happly(const float* __restrict__ x, const float* __restrict__ gamma,
                       const float* __restrict__ beta) {
    __shared__ float tl[64][33];
    const int b = blockIdx.z, t0 = blockIdx.x * 32, c0 = blockIdx.y * 64;
    const int tx = threadIdx.x, ty = threadIdx.y;
#pragma unroll
    for (int k = 0; k < 8; k++) {
        int cl = ty + k * 8;
        int c = c0 + cl;
        float ga = gamma[c] * g_inv[b * 32 + (c >> 4)];
        float be = beta[c] - g_mean[b * 32 + (c >> 4)] * ga;
        float v = x[((size_t)b * Cn + c) * Tn + t0 + tx];
        tl[cl][tx] = v * ga + be;
    }
    __syncthreads();
#pragma unroll
    for (int k = 0; k < 4; k++) {
        int t = t0 + ty + k * 8;
        __align__(4) fp16 p[2] = {
            __float2half_rn(tl[tx * 2 + 0][ty + k * 8]),
            __float2half_rn(tl[tx * 2 + 1][ty + k * 8])};
        size_t o = ((size_t)b * Tn + t) * Cn + c0 + tx * 2;
        *(uint32_t*)(g_hT + o) = *(uint32_t*)p;
    }
}

#define STG_A 16384
#define STG_AB 32768
#define NSTAGE 3
#define SMEM_SZ (NSTAGE * STG_AB)   // 98304
#define NTHR 128

// ---------------- shared mainloop (inlined) ---------------------------------
// CTA tile 128x128, BK=64, 4 warps (2m x 2n), warp tile 64x64; K-major SW.
// LDSM addresses hoisted into registers; per-kk update is a single XOR
// (swizzle delta (c_prev^c_next)<<4 = 0x20/0x60 alternating, row-independent).
__device__ __forceinline__ void run_mainloop(
    uint32_t sb, int tid, int wm, int wn,
    const char* Ap0, const char* Bp0, int S, size_t la2, size_t lb2,
    float acc[4][8][4]) {
    int lane = tid & 31;
    auto load_part = [&](int s, int buf, int part) {  // part in [0,4): 2 pairs each
        size_t kb = (size_t)s << 7;
        const char* Ap = Ap0 + kb;
        const char* Bp = Bp0 + kb;
        uint32_t ab = sb + buf * STG_AB;
        uint32_t bb = ab + STG_A;
#pragma unroll
        for (int j = part * 2; j < part * 2 + 2; j++) {
            int g = tid + j * NTHR;
            int r = g >> 3, c = g & 7;
            uint32_t sw = (uint32_t)(r * 128 + ((c ^ (r & 7)) << 4));
            cp16(ab + sw, Ap + (size_t)r * la2 + c * 16);
            cp16(bb + sw, Bp + (size_t)r * lb2 + c * 16);
        }
    };
    auto load_all = [&](int s, int buf) {
#pragma unroll
        for (int p = 0; p < 4; p++) load_part(s, buf, p);
    };

#pragma unroll
    for (int i = 0; i < 4; i++)
#pragma unroll
        for (int j = 0; j < 8; j++)
#pragma unroll
            for (int q = 0; q < 4; q++) acc[i][j][q] = 0.f;

    // hoisted ldmatrix offsets (kk = 0 values); XOR-updated per kk
    uint32_t offA[4], offB[4];
#pragma unroll
    for (int mi = 0; mi < 4; mi++) {
        int r = wm + mi * 16 + (lane & 15);
        int c = lane >> 4;
        offA[mi] = (uint32_t)(r * 128 + ((c ^ (r & 7)) << 4));
    }
#pragma unroll
    for (int nj = 0; nj < 4; nj++) {
        int r = wn + nj * 16 + (lane & 7) + ((lane >> 4) << 3);
        int c = (lane >> 3) & 1;
        offB[nj] = (uint32_t)(r * 128 + ((c ^ (r & 7)) << 4));
    }

    load_all(0, 0);
    asm volatile("cp.async.commit_group;");
    load_all(1, 1);
    asm volatile("cp.async.commit_group;");

    int cur = 0;
    for (int s = 0; s < S; s++) {
        asm volatile("cp.async.wait_group 1;");
        __syncthreads();
        const bool pf = (s + 2 < S);
        const int nb = (cur + 2) % NSTAGE;
        const uint32_t ab = sb + cur * STG_AB;
        const uint32_t bb = ab + STG_A;
#pragma unroll
        for (int kk = 0; kk < 4; kk++) {
            const uint32_t dx = (kk & 1) ? 0x60u : 0x20u;  // delta to NEXT kk
            uint32_t af[4][4], bfr[4][4];
#pragma unroll
            for (int mi = 0; mi < 4; mi++) {
                LDSM4(af[mi], ab + offA[mi]);
                offA[mi] ^= dx;
            }
#pragma unroll
            for (int nj = 0; nj < 4; nj++) {
                LDSM4(bfr[nj], bb + offB[nj]);
                offB[nj] ^= dx;
            }
            if (pf) load_part(s + 2, nb, kk);
#pragma unroll
            for (int mi = 0; mi < 4; mi++)
#pragma unroll
                for (int nj = 0; nj < 4; nj++) {
                    MMA16816(acc[mi][nj * 2 + 0], af[mi], bfr[nj][0], bfr[nj][1]);
                    MMA16816(acc[mi][nj * 2 + 1], af[mi], bfr[nj][2], bfr[nj][3]);
                }
        }
        // after 4 XORs (0x20^0x60^0x20^0x60 = 0) offsets are back at kk=0
        asm volatile("cp.async.commit_group;");
        cur = (cur + 1 == NSTAGE) ? 0 : cur + 1;
    }
}

// ---------------- fused QKV projection kernel -------------------------------
__global__ __launch_bounds__(NTHR, 2) void qkv_gemm(
    const fp16* __restrict__ hT, const fp16* __restrict__ wqk,
    const fp16* __restrict__ wv, fp16* __restrict__ qk, fp16* __restrict__ vv,
    const float* __restrict__ qkb, const float* __restrict__ vb) {
    extern __shared__ char smem[];
    const uint32_t sb = s2u(smem);
    const int tid = threadIdx.x, wid = tid >> 5, lane = tid & 31;
    const int wm = (wid >> 1) * 64, wn = (wid & 1) * 64;

    const int id = blockIdx.x;
    const bool isV = id >= 1024;
    int m0, n0, b, ldc;
    const fp16 *Ah, *Bh;
    fp16* Oh;
    size_t sA, sB, sC;
    const float* biasp;
    if (!isV) {          // QK: D[t, c_out]
        n0 = (id & 7) * 128;
        m0 = ((id >> 3) & 15) * 128;
        b = id >> 7;
        Ah = hT; Bh = wqk; Oh = qk;
        sA = CT; sB = 0; sC = QKT; ldc = QKC;
        biasp = qkb;
    } else {             // V: D[c_out, t]
        int id2 = id - 1024;
        n0 = (id2 & 15) * 128;
        m0 = ((id2 >> 4) & 3) * 128;
        b = id2 >> 6;
        Ah = wv; Bh = hT; Oh = vv;
        sA = 0; sB = CT; sC = CT; ldc = Tn;
        biasp = vb;
    }

    const char* Ap0 = (const char*)(Ah + (size_t)b * sA + (size_t)m0 * Cn);
    const char* Bp0 = (const char*)(Bh + (size_t)b * sB + (size_t)n0 * Cn);

    float acc[4][8][4];
    run_mainloop(sb, tid, wm, wn, Ap0, Bp0, Cn >> 6, Cn * 2, Cn * 2, acc);

    const int qr = lane >> 2, qc = (lane & 3) * 2;
#pragma unroll
    for (int mi = 0; mi < 4; mi++) {
#pragma unroll
        for (int ni = 0; ni < 8; ni++) {
            const int mA = m0 + wm + mi * 16 + qr;
            const int nA = n0 + wn + ni * 8 + qc;
#pragma unroll
            for (int h = 0; h < 2; h++) {
                const int m = mA + h * 8;
                float v0 = acc[mi][ni][h * 2 + 0];
                float v1 = acc[mi][ni][h * 2 + 1];
                if (isV) { float bv = biasp[m]; v0 += bv; v1 += bv; }
                else     { v0 += biasp[nA]; v1 += biasp[nA + 1]; }
                __align__(4) fp16 ph[2] = {__float2half_rn(v0), __float2half_rn(v1)};
                *(uint32_t*)(Oh + (size_t)b * sC + (size_t)m * ldc + nA) = *(uint32_t*)ph;
            }
        }
    }
}

// ---------------- general GEMM (scores / attnV / out-proj) ------------------
// OUT_MODE: 0 = fp32 + residual, 2 = fp16 exp + Z partials, 3 = 1/Z scaled fp16
template <int BIAS_MODE, bool HAS_RES, int OUT_MODE>
__global__ __launch_bounds__(NTHR, 2) void tgemm(
    const fp16* __restrict__ Ah, const fp16* __restrict__ Bh,
    float* __restrict__ Cf, fp16* __restrict__ Oh,
    int K, int lda, int ldb, int ldc,
    size_t sA, size_t sB, size_t sC,
    const float* __restrict__ bias, const float* __restrict__ res, size_t sRes,
    float* __restrict__ zp, float scale) {
    extern __shared__ char smem[];
    const uint32_t sb = s2u(smem);
    const int tid = threadIdx.x, wid = tid >> 5, lane = tid & 31;
    const int m0 = blockIdx.y * 128, n0 = blockIdx.x * 128, b = blockIdx.z;
    const int wm = (wid >> 1) * 64, wn = (wid & 1) * 64;

    const char* Ap0 = (const char*)(Ah + (size_t)b * sA + (size_t)m0 * lda);
    const char* Bp0 = (const char*)(Bh + (size_t)b * sB + (size_t)n0 * ldb);

    float acc[4][8][4];
    run_mainloop(sb, tid, wm, wn, Ap0, Bp0, K >> 6,
                 (size_t)lda * 2, (size_t)ldb * 2, acc);

    const int qr = lane >> 2, qc = (lane & 3) * 2;

    float rz[4][2];
    if (OUT_MODE == 3) {
#pragma unroll
        for (int mi = 0; mi < 4; mi++)
#pragma unroll
            for (int h = 0; h < 2; h++) {
                int m = m0 + wm + mi * 16 + h * 8 + qr;
                const float4* z4 = (const float4*)(zp + ((size_t)b * Tn + m) * 16);
                float4 a = z4[0], b4 = z4[1], c4 = z4[2], d4 = z4[3];
                float z = (a.x + a.y + a.z + a.w) + (b4.x + b4.y + b4.z + b4.w) +
                          (c4.x + c4.y + c4.z + c4.w) + (d4.x + d4.y + d4.z + d4.w);
                rz[mi][h] = 1.f / z;
            }
    }

    float rsum[4][2];
    if (OUT_MODE == 2) {
#pragma unroll
        for (int mi = 0; mi < 4; mi++)
#pragma unroll
            for (int h = 0; h < 2; h++) rsum[mi][h] = 0.f;
    }

#pragma unroll
    for (int mi = 0; mi < 4; mi++) {
#pragma unroll
        for (int ni = 0; ni < 8; ni++) {
            const int mA = m0 + wm + mi * 16 + qr;
            const int nA = n0 + wn + ni * 8 + qc;
#pragma unroll
            for (int h = 0; h < 2; h++) {
                const int m = mA + h * 8;
                float v0 = acc[mi][ni][h * 2 + 0] * scale;
                float v1 = acc[mi][ni][h * 2 + 1] * scale;
                if (BIAS_MODE == 1) { float bv = bias[m]; v0 += bv; v1 += bv; }
                const size_t go = (size_t)m * ldc + nA;
                if (OUT_MODE == 2) {
                    v0 = __expf(v0);
                    v1 = __expf(v1);
                    rsum[mi][h] += v0 + v1;
                    __align__(4) fp16 ph[2] = {__float2half_rn(v0), __float2half_rn(v1)};
                    *(uint32_t*)(Oh + (size_t)b * sC + go) = *(uint32_t*)ph;
                } else if (OUT_MODE == 3) {
                    v0 *= rz[mi][h];
                    v1 *= rz[mi][h];
                    __align__(4) fp16 ph[2] = {__float2half_rn(v0), __float2half_rn(v1)};
                    *(uint32_t*)(Oh + (size_t)b * sC + go) = *(uint32_t*)ph;
                } else {
                    if (HAS_RES) {
                        float2 r2 = *(const float2*)(res + (size_t)b * sRes + go);
                        v0 += r2.x; v1 += r2.y;
                    }
                    float2 o2 = {v0, v1};
                    *(float2*)(Cf + (size_t)b * sC + go) = o2;
                }
            }
        }
    }

    if (OUT_MODE == 2) {
#pragma unroll
        for (int mi = 0; mi < 4; mi++)
#pragma unroll
            for (int h = 0; h < 2; h++) {
                float v = rsum[mi][h];
                v += __shfl_xor_sync(0xffffffffu, v, 1);
                v += __shfl_xor_sync(0xffffffffu, v, 2);
                rsum[mi][h] = v;
            }
        __syncthreads();
        float* zsm = (float*)smem;  // [128][2]
        if ((lane & 3) == 0) {
#pragma unroll
            for (int mi = 0; mi < 4; mi++)
#pragma unroll
                for (int h = 0; h < 2; h++) {
                    int r = wm + mi * 16 + h * 8 + qr;
                    zsm[r * 2 + (wid & 1)] = rsum[mi][h];
                }
        }
        __syncthreads();
        float z = zsm[tid * 2] + zsm[tid * 2 + 1];
        zp[((size_t)b * Tn + m0 + tid) * 16 + blockIdx.x] = z;
    }
}

// ---------------- launch ----------------------------------------------------
template <typename T>
static T* sym_base(const void* sym) {
    void* p = nullptr;
    cudaGetSymbolAddress(&p, sym);
    return (T*)p;
}

extern "C" void kernel_launch(void* const* d_in, const int* in_sizes, int n_in,
                              void* d_out, int out_size) {
    const float* x = (const float*)d_in[0];
    const float* gamma = (const float*)d_in[1];
    const float* beta = (const float*)d_in[2];
    const float* q_w = (const float*)d_in[3];
    const float* q_b = (const float*)d_in[4];
    const float* k_w = (const float*)d_in[5];
    const float* k_b = (const float*)d_in[6];
    const float* v_w = (const float*)d_in[7];
    const float* v_b = (const float*)d_in[8];
    const float* o_w = (const float*)d_in[9];
    const float* o_b = (const float*)d_in[10];
    float* out = (float*)d_out;

    cudaFuncSetAttribute(qkv_gemm, cudaFuncAttributeMaxDynamicSharedMemorySize, SMEM_SZ);
    cudaFuncSetAttribute(tgemm<0, false, 2>, cudaFuncAttributeMaxDynamicSharedMemorySize, SMEM_SZ);
    cudaFuncSetAttribute(tgemm<0, false, 3>, cudaFuncAttributeMaxDynamicSharedMemorySize, SMEM_SZ);
    cudaFuncSetAttribute(tgemm<1, true, 0>, cudaFuncAttributeMaxDynamicSharedMemorySize, SMEM_SZ);

    fp16* hT = sym_base<fp16>(g_hT);
    fp16* wqk = sym_base<fp16>(g_wqk);
    fp16* wv = sym_base<fp16>(g_wv);
    fp16* wo = sym_base<fp16>(g_wo);
    fp16* qk = sym_base<fp16>(g_qk);
    fp16* vv = sym_base<fp16>(g_vv);
    fp16* aT = sym_base<fp16>(g_aT);
    fp16* wt = sym_base<fp16>(g_wt);
    float* zp = sym_base<float>(g_zp);
    float* qkb = sym_base<float>(g_qkb);

    // 0: weights convert + GN stats (fused)  1: GN apply+transpose
    prep<<<WCONV_BLKS + Bn * 32, 256>>>(q_w, k_w, v_w, o_w, q_b, k_b, x);
    happly<<<dim3(Tn / 32, Cn / 64, Bn), dim3(32, 8)>>>(x, gamma, beta);

    // 2: fused Q|K + V projections, one 1536-CTA launch
    qkv_gemm<<<1536, NTHR, SMEM_SZ>>>(hT, wqk, wv, qk, vv, qkb, v_b);

    // 3: Scores -> E = exp(S) fp16 + row partial sums
    dim3 gS(Tn / 128, Tn / 128, Bn);
    tgemm<0, false, 2><<<gS, NTHR, SMEM_SZ>>>(
        qk, qk + Cn, nullptr, wt,
        Cn, QKC, QKC, Tn, QKT, QKT, TT, nullptr, nullptr, 0, zp,
        1.f / sqrtf((float)Cn));

    // 4: Attn*V with per-row 1/Z normalization -> aT fp16
    dim3 gA(Cn / 128, Tn / 128, Bn);
    tgemm<0, false, 3><<<gA, NTHR, SMEM_SZ>>>(
        wt, vv, nullptr, aT,
        Tn, Tn, Tn, Cn, TT, CT, CT, nullptr, nullptr, 0, zp, 1.f);

    // 5: Out proj + bias + residual -> out fp32
    dim3 gO(Tn / 128, Cn / 128, Bn);
    tgemm<1, true, 0><<<gO, NTHR, SMEM_SZ>>>(
        wo, aT, out, nullptr,
        Cn, Cn, Cn, Tn, 0, CT, CT, o_b, x, CT, nullptr, 1.f);
}

// round 17
// speedup vs baseline: 1.5963x; 1.0058x over previous
#include <cuda_runtime.h>
#include <cuda_fp16.h>
#include <math.h>
#include <stdint.h>

#define Bn 8
#define Cn 512
#define Tn 2048
#define CT ((size_t)Cn * Tn)
#define TT ((size_t)Tn * Tn)
#define QKC 1024                         // stacked q|k channel dim
#define QKT ((size_t)Tn * QKC)           // per-batch qk plane

typedef __half fp16;

// ---------------- scratch (static device globals; allocation-guard safe) ----
__device__ __align__(16) fp16 g_hT[Bn * Tn * Cn];    // [B,T,C] groupnormed, fp16
__device__ __align__(16) fp16 g_wqk[QKC * Cn];       // [Wq;Wk] fp16
__device__ __align__(16) fp16 g_wv[Cn * Cn];
__device__ __align__(16) fp16 g_wo[Cn * Cn];
__device__ __align__(16) float g_qkb[QKC];           // [q_b;k_b]
__device__ __align__(16) fp16 g_qk[Bn * Tn * QKC];   // [B,T,1024] q|k
__device__ __align__(16) fp16 g_vv[Bn * Cn * Tn];    // [B,C,T]
__device__ __align__(16) fp16 g_aT[Bn * Tn * Cn];    // [B,T,C]
__device__ __align__(16) fp16 g_wt[Bn * Tn * Tn];    // E = exp(scores), unnormalized
__device__ __align__(16) float g_zp[(size_t)Bn * Tn * 16];  // row-sum partials
__device__ __align__(16) float g_mean[Bn * 32];
__device__ __align__(16) float g_inv[Bn * 32];

// ---------------- PTX helpers ----------------------------------------------
__device__ __forceinline__ uint32_t s2u(const void* p) {
    uint32_t a;
    asm("{ .reg .u64 t; cvta.to.shared.u64 t, %1; cvt.u32.u64 %0, t; }"
        : "=r"(a) : "l"(p));
    return a;
}

__device__ __forceinline__ void cp16(uint32_t d, const void* s) {
    asm volatile("cp.async.cg.shared.global [%0], [%1], 16;" :: "r"(d), "l"(s) : "memory");
}

#define LDSM4(r, addr)                                                          \
    asm volatile("ldmatrix.sync.aligned.m8n8.x4.shared.b16 {%0,%1,%2,%3}, [%4];"\
        : "=r"((r)[0]), "=r"((r)[1]), "=r"((r)[2]), "=r"((r)[3]) : "r"(addr))

#define MMA16816(d, a, b0, b1)                                                  \
    asm volatile(                                                               \
        "mma.sync.aligned.m16n8k16.row.col.f32.f16.f16.f32 "                    \
        "{%0,%1,%2,%3}, {%4,%5,%6,%7}, {%8,%9}, {%0,%1,%2,%3};"                 \
        : "+f"((d)[0]), "+f"((d)[1]), "+f"((d)[2]), "+f"((d)[3])                \
        : "r"((a)[0]), "r"((a)[1]), "r"((a)[2]), "r"((a)[3]),                   \
          "r"(b0), "r"(b1))

// ---------------- prep: weight convert + GN stats, one launch ---------------
#define WCONV_BLKS 4096
__global__ void prep(const float* __restrict__ qw, const float* __restrict__ kw,
                     const float* __restrict__ vw, const float* __restrict__ ow,
                     const float* __restrict__ qb, const float* __restrict__ kb,
                     const float* __restrict__ x) {
    const int n = Cn * Cn;
    if (blockIdx.x < WCONV_BLKS) {
        int i = blockIdx.x * blockDim.x + threadIdx.x;
        if (i < QKC) g_qkb[i] = (i < Cn) ? qb[i] : kb[i - Cn];
        int seg = i / n, j = i - seg * n;
        if (seg == 0)      g_wqk[j]     = __float2half_rn(qw[j]);
        else if (seg == 1) g_wqk[n + j] = __float2half_rn(kw[j]);
        else if (seg == 2) g_wv[j]      = __float2half_rn(vw[j]);
        else               g_wo[j]      = __float2half_rn(ow[j]);
        return;
    }
    const int bg = blockIdx.x - WCONV_BLKS, tid = threadIdx.x;
    const int b = bg >> 5, g = bg & 31;
    const size_t base = ((size_t)b * Cn + g * 16) * Tn;
    const float4* xv = (const float4*)(x + base);
    float s = 0.f, ss = 0.f;
    for (int i = tid; i < 8192; i += 256) {
        float4 v = xv[i];
        s += v.x + v.y + v.z + v.w;
        ss += v.x * v.x + v.y * v.y + v.z * v.z + v.w * v.w;
    }
    __shared__ float rs[256], rq[256];
    rs[tid] = s; rq[tid] = ss;
    __syncthreads();
    for (int o = 128; o > 0; o >>= 1) {
        if (tid < o) { rs[tid] += rs[tid + o]; rq[tid] += rq[tid + o]; }
        __syncthreads();
    }
    if (tid == 0) {
        float mean = rs[0] / 32768.f;
        float var = rq[0] / 32768.f - mean * mean;
        g_mean[bg] = mean;
        g_inv[bg] = rsqrtf(var + 1e-6f);
    }
}

// ---------------- GN apply + transpose -> fp16:  x[C,T] -> hT[T,C] ----------
__global__ void happly(const float* __restrict__ x, const float* __restrict__ gamma,
                       const float* __restrict__ beta) {
    __shared__ float tl[64][33];
    const int b = blockIdx.z, t0 = blockIdx.x * 32, c0 = blockIdx.y * 64;
    const int tx = threadIdx.x, ty = threadIdx.y;
#pragma unroll
    for (int k = 0; k < 8; k++) {
        int cl = ty + k * 8;
        int c = c0 + cl;
        float ga = gamma[c] * g_inv[b * 32 + (c >> 4)];
        float be = beta[c] - g_mean[b * 32 + (c >> 4)] * ga;
        float v = x[((size_t)b * Cn + c) * Tn + t0 + tx];
        tl[cl][tx] = v * ga + be;
    }
    __syncthreads();
#pragma unroll
    for (int k = 0; k < 4; k++) {
        int t = t0 + ty + k * 8;
        __align__(4) fp16 p[2] = {
            __float2half_rn(tl[tx * 2 + 0][ty + k * 8]),
            __float2half_rn(tl[tx * 2 + 1][ty + k * 8])};
        size_t o = ((size_t)b * Tn + t) * Cn + c0 + tx * 2;
        *(uint32_t*)(g_hT + o) = *(uint32_t*)p;
    }
}

#define STG_A 16384
#define STG_AB 32768
#define NSTAGE 3
#define SMEM_SZ (NSTAGE * STG_AB)   // 98304
#define NTHR 128

// ---------------- shared mainloop (inlined) ---------------------------------
// CTA tile 128x128, BK=64, 4 warps (2m x 2n), warp tile 64x64; K-major SW.
// LDSM addresses: hoisted + single-XOR update per kk.
// cp.async addresses: strength-reduced — c=tid&7 and r&7 are j-invariant, so
//   smem off = sw0 + j*2048 (immediate), global = gX + kb + j*stepX.
__device__ __forceinline__ void run_mainloop(
    uint32_t sb, int tid, int wm, int wn,
    const char* Ap0, const char* Bp0, int S, size_t la2, size_t lb2,
    float acc[4][8][4]) {
    int lane = tid & 31;

    // hoisted loader bases
    const int r0 = tid >> 3, cc = tid & 7;
    const uint32_t sw0 = (uint32_t)(r0 * 128 + ((cc ^ (r0 & 7)) << 4));
    const char* gA = Ap0 + (size_t)r0 * la2 + cc * 16;
    const char* gB = Bp0 + (size_t)r0 * lb2 + cc * 16;
    const size_t stepA = la2 << 4, stepB = lb2 << 4;  // 16 rows per j

    auto load_part = [&](int s, int buf, int part) {  // part in [0,4): 2 js each
        const size_t kb = (size_t)s << 7;
        const uint32_t ab = sb + buf * STG_AB + sw0;
        const uint32_t bb = ab + STG_A;
#pragma unroll
        for (int j = part * 2; j < part * 2 + 2; j++) {
            cp16(ab + j * 2048, gA + kb + j * stepA);
            cp16(bb + j * 2048, gB + kb + j * stepB);
        }
    };
    auto load_all = [&](int s, int buf) {
#pragma unroll
        for (int p = 0; p < 4; p++) load_part(s, buf, p);
    };

#pragma unroll
    for (int i = 0; i < 4; i++)
#pragma unroll
        for (int j = 0; j < 8; j++)
#pragma unroll
            for (int q = 0; q < 4; q++) acc[i][j][q] = 0.f;

    // hoisted ldmatrix offsets (kk = 0 values); XOR-updated per kk
    uint32_t offA[4], offB[4];
#pragma unroll
    for (int mi = 0; mi < 4; mi++) {
        int r = wm + mi * 16 + (lane & 15);
        int c = lane >> 4;
        offA[mi] = (uint32_t)(r * 128 + ((c ^ (r & 7)) << 4));
    }
#pragma unroll
    for (int nj = 0; nj < 4; nj++) {
        int r = wn + nj * 16 + (lane & 7) + ((lane >> 4) << 3);
        int c = (lane >> 3) & 1;
        offB[nj] = (uint32_t)(r * 128 + ((c ^ (r & 7)) << 4));
    }

    load_all(0, 0);
    asm volatile("cp.async.commit_group;");
    load_all(1, 1);
    asm volatile("cp.async.commit_group;");

    int cur = 0;
    for (int s = 0; s < S; s++) {
        asm volatile("cp.async.wait_group 1;");
        __syncthreads();
        const bool pf = (s + 2 < S);
        const int nb = (cur + 2) % NSTAGE;
        const uint32_t ab = sb + cur * STG_AB;
        const uint32_t bb = ab + STG_A;
#pragma unroll
        for (int kk = 0; kk < 4; kk++) {
            const uint32_t dx = (kk & 1) ? 0x60u : 0x20u;  // delta to NEXT kk
            uint32_t af[4][4], bfr[4][4];
#pragma unroll
            for (int mi = 0; mi < 4; mi++) {
                LDSM4(af[mi], ab + offA[mi]);
                offA[mi] ^= dx;
            }
#pragma unroll
            for (int nj = 0; nj < 4; nj++) {
                LDSM4(bfr[nj], bb + offB[nj]);
                offB[nj] ^= dx;
            }
            if (pf) load_part(s + 2, nb, kk);
#pragma unroll
            for (int mi = 0; mi < 4; mi++)
#pragma unroll
                for (int nj = 0; nj < 4; nj++) {
                    MMA16816(acc[mi][nj * 2 + 0], af[mi], bfr[nj][0], bfr[nj][1]);
                    MMA16816(acc[mi][nj * 2 + 1], af[mi], bfr[nj][2], bfr[nj][3]);
                }
        }
        // after 4 XORs (0x20^0x60^0x20^0x60 = 0) offsets are back at kk=0
        asm volatile("cp.async.commit_group;");
        cur = (cur + 1 == NSTAGE) ? 0 : cur + 1;
    }
}

// ---------------- fused QKV projection kernel -------------------------------
__global__ __launch_bounds__(NTHR, 2) void qkv_gemm(
    const fp16* __restrict__ hT, const fp16* __restrict__ wqk,
    const fp16* __restrict__ wv, fp16* __restrict__ qk, fp16* __restrict__ vv,
    const float* __restrict__ qkb, const float* __restrict__ vb) {
    extern __shared__ char smem[];
    const uint32_t sb = s2u(smem);
    const int tid = threadIdx.x, wid = tid >> 5, lane = tid & 31;
    const int wm = (wid >> 1) * 64, wn = (wid & 1) * 64;

    const int id = blockIdx.x;
    const bool isV = id >= 1024;
    int m0, n0, b, ldc;
    const fp16 *Ah, *Bh;
    fp16* Oh;
    size_t sA, sB, sC;
    const float* biasp;
    if (!isV) {          // QK: D[t, c_out]
        n0 = (id & 7) * 128;
        m0 = ((id >> 3) & 15) * 128;
        b = id >> 7;
        Ah = hT; Bh = wqk; Oh = qk;
        sA = CT; sB = 0; sC = QKT; ldc = QKC;
        biasp = qkb;
    } else {             // V: D[c_out, t]
        int id2 = id - 1024;
        n0 = (id2 & 15) * 128;
        m0 = ((id2 >> 4) & 3) * 128;
        b = id2 >> 6;
        Ah = wv; Bh = hT; Oh = vv;
        sA = 0; sB = CT; sC = CT; ldc = Tn;
        biasp = vb;
    }

    const char* Ap0 = (const char*)(Ah + (size_t)b * sA + (size_t)m0 * Cn);
    const char* Bp0 = (const char*)(Bh + (size_t)b * sB + (size_t)n0 * Cn);

    float acc[4][8][4];
    run_mainloop(sb, tid, wm, wn, Ap0, Bp0, Cn >> 6, Cn * 2, Cn * 2, acc);

    const int qr = lane >> 2, qc = (lane & 3) * 2;
#pragma unroll
    for (int mi = 0; mi < 4; mi++) {
#pragma unroll
        for (int ni = 0; ni < 8; ni++) {
            const int mA = m0 + wm + mi * 16 + qr;
            const int nA = n0 + wn + ni * 8 + qc;
#pragma unroll
            for (int h = 0; h < 2; h++) {
                const int m = mA + h * 8;
                float v0 = acc[mi][ni][h * 2 + 0];
                float v1 = acc[mi][ni][h * 2 + 1];
                if (isV) { float bv = biasp[m]; v0 += bv; v1 += bv; }
                else     { v0 += biasp[nA]; v1 += biasp[nA + 1]; }
                __align__(4) fp16 ph[2] = {__float2half_rn(v0), __float2half_rn(v1)};
                *(uint32_t*)(Oh + (size_t)b * sC + (size_t)m * ldc + nA) = *(uint32_t*)ph;
            }
        }
    }
}

// ---------------- general GEMM (scores / attnV / out-proj) ------------------
// OUT_MODE: 0 = fp32 + residual, 2 = fp16 exp + Z partials, 3 = 1/Z scaled fp16
template <int BIAS_MODE, bool HAS_RES, int OUT_MODE>
__global__ __launch_bounds__(NTHR, 2) void tgemm(
    const fp16* __restrict__ Ah, const fp16* __restrict__ Bh,
    float* __restrict__ Cf, fp16* __restrict__ Oh,
    int K, int lda, int ldb, int ldc,
    size_t sA, size_t sB, size_t sC,
    const float* __restrict__ bias, const float* __restrict__ res, size_t sRes,
    float* __restrict__ zp, float scale) {
    extern __shared__ char smem[];
    const uint32_t sb = s2u(smem);
    const int tid = threadIdx.x, wid = tid >> 5, lane = tid & 31;
    const int m0 = blockIdx.y * 128, n0 = blockIdx.x * 128, b = blockIdx.z;
    const int wm = (wid >> 1) * 64, wn = (wid & 1) * 64;

    const char* Ap0 = (const char*)(Ah + (size_t)b * sA + (size_t)m0 * lda);
    const char* Bp0 = (const char*)(Bh + (size_t)b * sB + (size_t)n0 * ldb);

    float acc[4][8][4];
    run_mainloop(sb, tid, wm, wn, Ap0, Bp0, K >> 6,
                 (size_t)lda * 2, (size_t)ldb * 2, acc);

    const int qr = lane >> 2, qc = (lane & 3) * 2;

    float rz[4][2];
    if (OUT_MODE == 3) {
#pragma unroll
        for (int mi = 0; mi < 4; mi++)
#pragma unroll
            for (int h = 0; h < 2; h++) {
                int m = m0 + wm + mi * 16 + h * 8 + qr;
                const float4* z4 = (const float4*)(zp + ((size_t)b * Tn + m) * 16);
                float4 a = z4[0], b4 = z4[1], c4 = z4[2], d4 = z4[3];
                float z = (a.x + a.y + a.z + a.w) + (b4.x + b4.y + b4.z + b4.w) +
                          (c4.x + c4.y + c4.z + c4.w) + (d4.x + d4.y + d4.z + d4.w);
                rz[mi][h] = 1.f / z;
            }
    }

    float rsum[4][2];
    if (OUT_MODE == 2) {
#pragma unroll
        for (int mi = 0; mi < 4; mi++)
#pragma unroll
            for (int h = 0; h < 2; h++) rsum[mi][h] = 0.f;
    }

#pragma unroll
    for (int mi = 0; mi < 4; mi++) {
#pragma unroll
        for (int ni = 0; ni < 8; ni++) {
            const int mA = m0 + wm + mi * 16 + qr;
            const int nA = n0 + wn + ni * 8 + qc;
#pragma unroll
            for (int h = 0; h < 2; h++) {
                const int m = mA + h * 8;
                float v0 = acc[mi][ni][h * 2 + 0] * scale;
                float v1 = acc[mi][ni][h * 2 + 1] * scale;
                if (BIAS_MODE == 1) { float bv = bias[m]; v0 += bv; v1 += bv; }
                const size_t go = (size_t)m * ldc + nA;
                if (OUT_MODE == 2) {
                    v0 = __expf(v0);
                    v1 = __expf(v1);
                    rsum[mi][h] += v0 + v1;
                    __align__(4) fp16 ph[2] = {__float2half_rn(v0), __float2half_rn(v1)};
                    *(uint32_t*)(Oh + (size_t)b * sC + go) = *(uint32_t*)ph;
                } else if (OUT_MODE == 3) {
                    v0 *= rz[mi][h];
                    v1 *= rz[mi][h];
                    __align__(4) fp16 ph[2] = {__float2half_rn(v0), __float2half_rn(v1)};
                    *(uint32_t*)(Oh + (size_t)b * sC + go) = *(uint32_t*)ph;
                } else {
                    if (HAS_RES) {
                        float2 r2 = *(const float2*)(res + (size_t)b * sRes + go);
                        v0 += r2.x; v1 += r2.y;
                    }
                    float2 o2 = {v0, v1};
                    *(float2*)(Cf + (size_t)b * sC + go) = o2;
                }
            }
        }
    }

    if (OUT_MODE == 2) {
#pragma unroll
        for (int mi = 0; mi < 4; mi++)
#pragma unroll
            for (int h = 0; h < 2; h++) {
                float v = rsum[mi][h];
                v += __shfl_xor_sync(0xffffffffu, v, 1);
                v += __shfl_xor_sync(0xffffffffu, v, 2);
                rsum[mi][h] = v;
            }
        __syncthreads();
        float* zsm = (float*)smem;  // [128][2]
        if ((lane & 3) == 0) {
#pragma unroll
            for (int mi = 0; mi < 4; mi++)
#pragma unroll
                for (int h = 0; h < 2; h++) {
                    int r = wm + mi * 16 + h * 8 + qr;
                    zsm[r * 2 + (wid & 1)] = rsum[mi][h];
                }
        }
        __syncthreads();
        float z = zsm[tid * 2] + zsm[tid * 2 + 1];
        zp[((size_t)b * Tn + m0 + tid) * 16 + blockIdx.x] = z;
    }
}

// ---------------- launch ----------------------------------------------------
template <typename T>
static T* sym_base(const void* sym) {
    void* p = nullptr;
    cudaGetSymbolAddress(&p, sym);
    return (T*)p;
}

extern "C" void kernel_launch(void* const* d_in, const int* in_sizes, int n_in,
                              void* d_out, int out_size) {
    const float* x = (const float*)d_in[0];
    const float* gamma = (const float*)d_in[1];
    const float* beta = (const float*)d_in[2];
    const float* q_w = (const float*)d_in[3];
    const float* q_b = (const float*)d_in[4];
    const float* k_w = (const float*)d_in[5];
    const float* k_b = (const float*)d_in[6];
    const float* v_w = (const float*)d_in[7];
    const float* v_b = (const float*)d_in[8];
    const float* o_w = (const float*)d_in[9];
    const float* o_b = (const float*)d_in[10];
    float* out = (float*)d_out;

    cudaFuncSetAttribute(qkv_gemm, cudaFuncAttributeMaxDynamicSharedMemorySize, SMEM_SZ);
    cudaFuncSetAttribute(tgemm<0, false, 2>, cudaFuncAttributeMaxDynamicSharedMemorySize, SMEM_SZ);
    cudaFuncSetAttribute(tgemm<0, false, 3>, cudaFuncAttributeMaxDynamicSharedMemorySize, SMEM_SZ);
    cudaFuncSetAttribute(tgemm<1, true, 0>, cudaFuncAttributeMaxDynamicSharedMemorySize, SMEM_SZ);

    fp16* hT = sym_base<fp16>(g_hT);
    fp16* wqk = sym_base<fp16>(g_wqk);
    fp16* wv = sym_base<fp16>(g_wv);
    fp16* wo = sym_base<fp16>(g_wo);
    fp16* qk = sym_base<fp16>(g_qk);
    fp16* vv = sym_base<fp16>(g_vv);
    fp16* aT = sym_base<fp16>(g_aT);
    fp16* wt = sym_base<fp16>(g_wt);
    float* zp = sym_base<float>(g_zp);
    float* qkb = sym_base<float>(g_qkb);

    // 0: weights convert + GN stats (fused)  1: GN apply+transpose
    prep<<<WCONV_BLKS + Bn * 32, 256>>>(q_w, k_w, v_w, o_w, q_b, k_b, x);
    happly<<<dim3(Tn / 32, Cn / 64, Bn), dim3(32, 8)>>>(x, gamma, beta);

    // 2: fused Q|K + V projections, one 1536-CTA launch
    qkv_gemm<<<1536, NTHR, SMEM_SZ>>>(hT, wqk, wv, qk, vv, qkb, v_b);

    // 3: Scores -> E = exp(S) fp16 + row partial sums
    dim3 gS(Tn / 128, Tn / 128, Bn);
    tgemm<0, false, 2><<<gS, NTHR, SMEM_SZ>>>(
        qk, qk + Cn, nullptr, wt,
        Cn, QKC, QKC, Tn, QKT, QKT, TT, nullptr, nullptr, 0, zp,
        1.f / sqrtf((float)Cn));

    // 4: Attn*V with per-row 1/Z normalization -> aT fp16
    dim3 gA(Cn / 128, Tn / 128, Bn);
    tgemm<0, false, 3><<<gA, NTHR, SMEM_SZ>>>(
        wt, vv, nullptr, aT,
        Tn, Tn, Tn, Cn, TT, CT, CT, nullptr, nullptr, 0, zp, 1.f);

    // 5: Out proj + bias + residual -> out fp32
    dim3 gO(Tn / 128, Cn / 128, Bn);
    tgemm<1, true, 0><<<gO, NTHR, SMEM_SZ>>>(
        wo, aT, out, nullptr,
        Cn, Cn, Cn, Tn, 0, CT, CT, o_b, x, CT, nullptr, 1.f);
}